// round 5
// baseline (speedup 1.0000x reference)
#include <cuda_runtime.h>
#include <math.h>

#define M_TOT 32768
#define N_PTS 8192
#define KK    16
#define TILE  2048
#define CIN   32
#define CO    64
#define EIN   35

// scratch: KNN indices (2 MB)
__device__ int g_knn[M_TOT * KK];

__device__ __forceinline__ float gelu_tanh(float x) {
    float x3 = x * x * x;
    float t  = tanhf(0.7978845608028654f * (x + 0.044715f * x3));
    return 0.5f * x * (1.0f + t);
}

// order-preserving float -> uint32 (handles tiny negative d2 from rounding)
__device__ __forceinline__ unsigned int f2ord(float f) {
    unsigned int u = __float_as_uint(f);
    return (u & 0x80000000u) ? ~u : (u | 0x80000000u);
}

// ---------------------------------------------------------------------------
// Kernel 1: brute-force KNN, 2 threads per grid vertex (parity-split over the
// point stream), private top-16 lists merged by rank-selection on packed
// (d2, idx) keys. Distance mimics the reference: (|q|^2+|r|^2) - 2*q.r in
// scaled coords (scale 32 = exact power of two).
// NOTE: the merge key buffer ALIASES the point-tile buffer (sp is dead after
// the scan loop) to stay under the 48KB static smem limit.
// ---------------------------------------------------------------------------
__global__ __launch_bounds__(128) void knn_kernel(const float* __restrict__ verts,
                                                  const float* __restrict__ gverts) {
    __shared__ __align__(16) float4 sp[TILE];            // 32 KB (reused below)

    const int tid = threadIdx.x;
    const int ml  = tid >> 1;          // local m (0..63)
    const int par = tid & 1;           // parity half
    const int m   = blockIdx.x * 64 + ml;

    const float qx = __fmul_rn(gverts[m * 3 + 0], 32.0f);
    const float qy = __fmul_rn(gverts[m * 3 + 1], 32.0f);
    const float qz = __fmul_rn(gverts[m * 3 + 2], 32.0f);
    const float A  = __fadd_rn(__fadd_rn(__fmul_rn(qx, qx), __fmul_rn(qy, qy)),
                               __fmul_rn(qz, qz));

    float bd[KK];
    int   bi[KK];
#pragma unroll
    for (int t = 0; t < KK; t++) { bd[t] = 3.0e38f; bi[t] = 0; }
    float worst = 3.0e38f;
    int   wpos  = 0;

    for (int base = 0; base < N_PTS; base += TILE) {
        __syncthreads();
        for (int i = tid; i < TILE; i += 128) {
            float rx = __fmul_rn(verts[(base + i) * 3 + 0], 32.0f);
            float ry = __fmul_rn(verts[(base + i) * 3 + 1], 32.0f);
            float rz = __fmul_rn(verts[(base + i) * 3 + 2], 32.0f);
            float B  = __fadd_rn(__fadd_rn(__fmul_rn(rx, rx), __fmul_rn(ry, ry)),
                                 __fmul_rn(rz, rz));
            sp[i] = make_float4(rx, ry, rz, B);
        }
        __syncthreads();

#pragma unroll 8
        for (int j = 0; j < TILE; j += 2) {
            float4 p = sp[j + par];
            float  D  = fmaf(qz, p.z, fmaf(qy, p.y, __fmul_rn(qx, p.x)));
            float  d2 = __fsub_rn(__fadd_rn(A, p.w), __fmul_rn(2.0f, D));
            if (d2 < worst) {
                int jj = base + j + par;
#pragma unroll
                for (int t = 0; t < KK; t++)
                    if (t == wpos) { bd[t] = d2; bi[t] = jj; }
                worst = bd[0]; wpos = 0;
#pragma unroll
                for (int t = 1; t < KK; t++)
                    if (bd[t] > worst) { worst = bd[t]; wpos = t; }
            }
        }
    }

    // sp is dead from here on: all threads are past the last tile scan.
    __syncthreads();
    unsigned long long (*skey)[33] =
        reinterpret_cast<unsigned long long (*)[33]>(sp);  // 64*33*8 = 16896 B <= 32 KB

    // ---- publish packed keys: (ordered d2) << 32 | idx  (idx < 2^13) ----
#pragma unroll
    for (int t = 0; t < KK; t++)
        skey[ml][par * KK + t] =
            ((unsigned long long)f2ord(bd[t]) << 32) | (unsigned int)bi[t];
    __syncwarp();   // pair (tid, tid^1) lives in the same warp

    // ---- rank-select: candidate with rank < 16 goes to slot 'rank' ----
    int rank[KK];
#pragma unroll
    for (int t = 0; t < KK; t++) rank[t] = 0;
    unsigned long long mykey[KK];
#pragma unroll
    for (int t = 0; t < KK; t++) mykey[t] = skey[ml][par * KK + t];
#pragma unroll 4
    for (int k = 0; k < 2 * KK; k++) {
        unsigned long long other = skey[ml][k];
#pragma unroll
        for (int t = 0; t < KK; t++) rank[t] += (other < mykey[t]);
    }
#pragma unroll
    for (int t = 0; t < KK; t++)
        if (rank[t] < KK) g_knn[m * KK + rank[t]] = bi[t];
}

// ---------------------------------------------------------------------------
// Kernel 2: gather + edge MLP (L1 -> LN -> GELU -> mean) -> edge L2 -> concat
// grid_feat -> out MLP. One warp per vertex, 8 vertices per 256-thread block.
// Key trick: mean-before-ew2 (linear) cuts edge layer-2 MACs by 16x.
// ---------------------------------------------------------------------------
__global__ __launch_bounds__(256) void mlp_kernel(
    const float* __restrict__ verts, const float* __restrict__ feats,
    const float* __restrict__ gverts, const float* __restrict__ gfeat,
    const float* __restrict__ ew1, const float* __restrict__ eb1,
    const float* __restrict__ eg1, const float* __restrict__ ebt1,
    const float* __restrict__ ew2, const float* __restrict__ eb2,
    const float* __restrict__ ow1, const float* __restrict__ ob1,
    const float* __restrict__ og1, const float* __restrict__ obt1,
    const float* __restrict__ ow2, const float* __restrict__ ob2,
    float* __restrict__ out)
{
    __shared__ float s_w1[EIN * CO];                      //  8960 B
    __shared__ float s_w2[CO * CO];                       // 16384 B
    __shared__ __align__(16) float s_et[8][EIN + 1][KK];  // 18432 B (transposed e)
    __shared__ float s_buf[8][CO];                        //  2048 B

    const int tid = threadIdx.x;
    for (int i = tid; i < EIN * CO; i += 256) s_w1[i] = ew1[i];
    for (int i = tid; i < CO * CO; i += 256) s_w2[i] = ew2[i];

    const int w    = tid >> 5;
    const int lane = tid & 31;
    const int m    = blockIdx.x * 8 + w;
    const int c0   = lane * 2;

    const float2 p_eb1  = *(const float2*)(eb1  + c0);
    const float2 p_eg1  = *(const float2*)(eg1  + c0);
    const float2 p_ebt1 = *(const float2*)(ebt1 + c0);
    const float2 p_eb2  = *(const float2*)(eb2  + c0);
    const float2 p_ob1  = *(const float2*)(ob1  + c0);
    const float2 p_og1  = *(const float2*)(og1  + c0);
    const float2 p_obt1 = *(const float2*)(obt1 + c0);
    const float2 p_ob2  = *(const float2*)(ob2  + c0);

    // ---- gather: 2 lanes per neighbor row; transposed smem layout ----
    {
        const int row  = lane >> 1;
        const int half = lane & 1;
        const int idx  = g_knn[m * KK + row];
        const float4* f4 = (const float4*)(feats + idx * CIN + half * 16);
        float4 a = f4[0], b = f4[1], c = f4[2], d = f4[3];
        const int ib = half * 16;
        float vals[16] = {a.x, a.y, a.z, a.w, b.x, b.y, b.z, b.w,
                          c.x, c.y, c.z, c.w, d.x, d.y, d.z, d.w};
#pragma unroll
        for (int t = 0; t < 16; t++) s_et[w][ib + t][row] = vals[t];
        if (half == 0) {
            s_et[w][32][row] = verts[idx * 3 + 0] - gverts[m * 3 + 0];
            s_et[w][33][row] = verts[idx * 3 + 1] - gverts[m * 3 + 1];
            s_et[w][34][row] = verts[idx * 3 + 2] - gverts[m * 3 + 2];
        }
    }
    __syncthreads();

    // ---- edge layer 1 + LN + GELU, accumulate mean over K ----
    float gb0 = 0.0f, gb1 = 0.0f;
#pragma unroll
    for (int pass = 0; pass < 2; pass++) {
        const int r0 = pass * 8;
        float acc0[8], acc1[8];
#pragma unroll
        for (int r = 0; r < 8; r++) { acc0[r] = p_eb1.x; acc1[r] = p_eb1.y; }
#pragma unroll
        for (int i = 0; i < EIN; i++) {
            float4 e0 = *(const float4*)&s_et[w][i][r0];
            float4 e1 = *(const float4*)&s_et[w][i][r0 + 4];
            float2 wv = *(const float2*)&s_w1[i * CO + c0];
            acc0[0] = fmaf(e0.x, wv.x, acc0[0]); acc1[0] = fmaf(e0.x, wv.y, acc1[0]);
            acc0[1] = fmaf(e0.y, wv.x, acc0[1]); acc1[1] = fmaf(e0.y, wv.y, acc1[1]);
            acc0[2] = fmaf(e0.z, wv.x, acc0[2]); acc1[2] = fmaf(e0.z, wv.y, acc1[2]);
            acc0[3] = fmaf(e0.w, wv.x, acc0[3]); acc1[3] = fmaf(e0.w, wv.y, acc1[3]);
            acc0[4] = fmaf(e1.x, wv.x, acc0[4]); acc1[4] = fmaf(e1.x, wv.y, acc1[4]);
            acc0[5] = fmaf(e1.y, wv.x, acc0[5]); acc1[5] = fmaf(e1.y, wv.y, acc1[5]);
            acc0[6] = fmaf(e1.z, wv.x, acc0[6]); acc1[6] = fmaf(e1.z, wv.y, acc1[6]);
            acc0[7] = fmaf(e1.w, wv.x, acc0[7]); acc1[7] = fmaf(e1.w, wv.y, acc1[7]);
        }
#pragma unroll
        for (int r = 0; r < 8; r++) {
            float a0 = acc0[r], a1 = acc1[r];
            float s  = a0 + a1;
            float ss = fmaf(a0, a0, a1 * a1);
#pragma unroll
            for (int o = 16; o > 0; o >>= 1) {
                s  += __shfl_xor_sync(0xffffffffu, s,  o);
                ss += __shfl_xor_sync(0xffffffffu, ss, o);
            }
            float mean = s * (1.0f / 64.0f);
            float var  = ss * (1.0f / 64.0f) - mean * mean;
            float rstd = rsqrtf(var + 1e-5f);
            float h0 = fmaf((a0 - mean) * rstd, p_eg1.x, p_ebt1.x);
            float h1 = fmaf((a1 - mean) * rstd, p_eg1.y, p_ebt1.y);
            gb0 += gelu_tanh(h0);
            gb1 += gelu_tanh(h1);
        }
    }
    gb0 *= (1.0f / 16.0f);
    gb1 *= (1.0f / 16.0f);
    s_buf[w][c0] = gb0; s_buf[w][c0 + 1] = gb1;
    __syncwarp();

    // ---- edge layer 2 on the mean (linear commutes with mean) ----
    float a0 = p_eb2.x, a1 = p_eb2.y;
#pragma unroll
    for (int i = 0; i < CO; i++) {
        float  g  = s_buf[w][i];
        float2 wv = *(const float2*)&s_w2[i * CO + c0];
        a0 = fmaf(g, wv.x, a0);
        a1 = fmaf(g, wv.y, a1);
    }
    __syncwarp();
    s_buf[w][c0] = a0; s_buf[w][c0 + 1] = a1;
    __syncwarp();

    // ---- out layer 1: agg @ ow1[0:64] + grid_feat @ ow1[64:160] + ob1 ----
    float o0 = p_ob1.x, o1 = p_ob1.y;
#pragma unroll
    for (int i = 0; i < CO; i++) {
        float  g  = s_buf[w][i];
        float2 wv = __ldg((const float2*)(ow1 + i * CO + c0));
        o0 = fmaf(g, wv.x, o0);
        o1 = fmaf(g, wv.y, o1);
    }
    const float* gf = gfeat + m * 96;
#pragma unroll 8
    for (int i = 0; i < 96; i++) {
        float  g  = __ldg(gf + i);
        float2 wv = __ldg((const float2*)(ow1 + (CO + i) * CO + c0));
        o0 = fmaf(g, wv.x, o0);
        o1 = fmaf(g, wv.y, o1);
    }
    {
        float s  = o0 + o1;
        float ss = fmaf(o0, o0, o1 * o1);
#pragma unroll
        for (int o = 16; o > 0; o >>= 1) {
            s  += __shfl_xor_sync(0xffffffffu, s,  o);
            ss += __shfl_xor_sync(0xffffffffu, ss, o);
        }
        float mean = s * (1.0f / 64.0f);
        float var  = ss * (1.0f / 64.0f) - mean * mean;
        float rstd = rsqrtf(var + 1e-5f);
        o0 = gelu_tanh(fmaf((o0 - mean) * rstd, p_og1.x, p_obt1.x));
        o1 = gelu_tanh(fmaf((o1 - mean) * rstd, p_og1.y, p_obt1.y));
    }
    __syncwarp();
    s_buf[w][c0] = o0; s_buf[w][c0 + 1] = o1;
    __syncwarp();

    // ---- out layer 2 ----
    float f0 = p_ob2.x, f1 = p_ob2.y;
#pragma unroll
    for (int i = 0; i < CO; i++) {
        float  g  = s_buf[w][i];
        float2 wv = __ldg((const float2*)(ow2 + i * CO + c0));
        f0 = fmaf(g, wv.x, f0);
        f1 = fmaf(g, wv.y, f1);
    }
    *(float2*)(out + m * CO + c0) = make_float2(f0, f1);
}

// ---------------------------------------------------------------------------
extern "C" void kernel_launch(void* const* d_in, const int* in_sizes, int n_in,
                              void* d_out, int out_size) {
    const float* vertices = (const float*)d_in[0];
    const float* features = (const float*)d_in[1];
    const float* gverts   = (const float*)d_in[2];
    const float* gfeat    = (const float*)d_in[3];
    const float* ew1  = (const float*)d_in[4];
    const float* eb1  = (const float*)d_in[5];
    const float* eg1  = (const float*)d_in[6];
    const float* ebt1 = (const float*)d_in[7];
    const float* ew2  = (const float*)d_in[8];
    const float* eb2  = (const float*)d_in[9];
    const float* ow1  = (const float*)d_in[10];
    const float* ob1  = (const float*)d_in[11];
    const float* og1  = (const float*)d_in[12];
    const float* obt1 = (const float*)d_in[13];
    const float* ow2  = (const float*)d_in[14];
    const float* ob2  = (const float*)d_in[15];
    float* out = (float*)d_out;

    knn_kernel<<<M_TOT / 64, 128>>>(vertices, gverts);
    mlp_kernel<<<M_TOT / 8, 256>>>(vertices, features, gverts, gfeat,
                                   ew1, eb1, eg1, ebt1, ew2, eb2,
                                   ow1, ob1, og1, obt1, ow2, ob2, out);
}

// round 9
// speedup vs baseline: 3.7758x; 3.7758x over previous
#include <cuda_runtime.h>
#include <math.h>

#define M_TOT 32768
#define N_PTS 8192
#define KK    16
#define CIN   32
#define CO    64
#define EIN   35
#define NC1   8
#define NCELLS 512

// scratch (all __device__, no allocs)
__device__ int    g_cellid[N_PTS];
__device__ int    g_cnt[NCELLS];
__device__ int    g_off[NCELLS + 1];
__device__ float4 g_pts[N_PTS];
__device__ int    g_pidx[N_PTS];
__device__ int    g_knn[M_TOT * KK];

__device__ __forceinline__ float gelu_tanh(float x) {
    float x3 = x * x * x;
    float t  = tanhf(0.7978845608028654f * (x + 0.044715f * x3));
    return 0.5f * x * (1.0f + t);
}

// order-preserving float -> uint32
__device__ __forceinline__ unsigned int f2ord(float f) {
    unsigned int u = __float_as_uint(f);
    return (u & 0x80000000u) ? ~u : (u | 0x80000000u);
}

// ---------------------------------------------------------------------------
// Binning pipeline: zero -> histogram -> scan -> scatter
// Cells: 8x8x8 over scaled coords [0,32]^3, cell width 4.0 (exact pow2 math).
// ---------------------------------------------------------------------------
__global__ void zero_kernel() { g_cnt[threadIdx.x] = 0; }

__global__ void hist_kernel(const float* __restrict__ verts) {
    int i = blockIdx.x * 256 + threadIdx.x;
    float rx = __fmul_rn(verts[i * 3 + 0], 32.0f);
    float ry = __fmul_rn(verts[i * 3 + 1], 32.0f);
    float rz = __fmul_rn(verts[i * 3 + 2], 32.0f);
    int cx = min(NC1 - 1, max(0, (int)(rx * 0.25f)));
    int cy = min(NC1 - 1, max(0, (int)(ry * 0.25f)));
    int cz = min(NC1 - 1, max(0, (int)(rz * 0.25f)));
    int c  = (cx * NC1 + cy) * NC1 + cz;
    g_cellid[i] = c;
    atomicAdd(&g_cnt[c], 1);
}

__global__ void scan_kernel() {   // 1 block, 512 threads: exclusive offsets
    __shared__ int s[NCELLS];
    int t = threadIdx.x;
    s[t] = g_cnt[t];
    __syncthreads();
    for (int o = 1; o < NCELLS; o <<= 1) {
        int x = (t >= o) ? s[t - o] : 0;
        __syncthreads();
        s[t] += x;
        __syncthreads();
    }
    g_off[t + 1] = s[t];
    if (t == 0) g_off[0] = 0;
    g_cnt[t] = 0;   // reset as scatter cursor
}

__global__ void scatter_kernel(const float* __restrict__ verts) {
    int i = blockIdx.x * 256 + threadIdx.x;
    float rx = __fmul_rn(verts[i * 3 + 0], 32.0f);
    float ry = __fmul_rn(verts[i * 3 + 1], 32.0f);
    float rz = __fmul_rn(verts[i * 3 + 2], 32.0f);
    float B  = __fadd_rn(__fadd_rn(__fmul_rn(rx, rx), __fmul_rn(ry, ry)),
                         __fmul_rn(rz, rz));
    int c   = g_cellid[i];
    int pos = g_off[c] + atomicAdd(&g_cnt[c], 1);
    g_pts[pos]  = make_float4(rx, ry, rz, B);
    g_pidx[pos] = i;
}

// ---------------------------------------------------------------------------
// KNN: 1 thread per grid vertex; CTA = 4x4x4 query tile sharing one home cell
// so every warp scans an identical point stream (broadcast loads). Ring
// expansion with exact coverage guarantee. Distance formula identical to the
// verified brute-force version: (|q|^2 + |r|^2) - 2*q.r in x32-scaled coords.
// Output canonicalized (sorted by (d2, idx)) => deterministic across runs and
// identical accumulation order to the reference's top_k.
// ---------------------------------------------------------------------------
__global__ __launch_bounds__(64) void knn_kernel(const float* __restrict__ gverts) {
    const int ix = blockIdx.x * 4 + threadIdx.x;
    const int iy = blockIdx.y * 4 + threadIdx.y;
    const int iz = blockIdx.z * 4 + threadIdx.z;
    const int m  = (ix * 32 + iy) * 32 + iz;

    const float qx = __fmul_rn(gverts[m * 3 + 0], 32.0f);
    const float qy = __fmul_rn(gverts[m * 3 + 1], 32.0f);
    const float qz = __fmul_rn(gverts[m * 3 + 2], 32.0f);
    const float A  = __fadd_rn(__fadd_rn(__fmul_rn(qx, qx), __fmul_rn(qy, qy)),
                               __fmul_rn(qz, qz));

    const int cx = min(NC1 - 1, max(0, (int)(qx * 0.25f)));
    const int cy = min(NC1 - 1, max(0, (int)(qy * 0.25f)));
    const int cz = min(NC1 - 1, max(0, (int)(qz * 0.25f)));

    float bd[KK];
    int   bi[KK];
#pragma unroll
    for (int t = 0; t < KK; t++) { bd[t] = 3.0e38f; bi[t] = 0; }
    float worst = 3.0e38f;
    int   wpos  = 0;

    int px0 = 1, px1 = 0, py0 = 1, py1 = 0, pz0 = 1, pz1 = 0;  // empty prev box

    for (int r = 1; r <= NC1; r++) {
        const int nx0 = max(cx - r, 0), nx1 = min(cx + r, NC1 - 1);
        const int ny0 = max(cy - r, 0), ny1 = min(cy + r, NC1 - 1);
        const int nz0 = max(cz - r, 0), nz1 = min(cz + r, NC1 - 1);

        for (int x = nx0; x <= nx1; x++)
        for (int y = ny0; y <= ny1; y++)
        for (int z = nz0; z <= nz1; z++) {
            if (x >= px0 && x <= px1 && y >= py0 && y <= py1 &&
                z >= pz0 && z <= pz1) continue;   // already scanned
            const int c = (x * NC1 + y) * NC1 + z;
            const int s = g_off[c], e = g_off[c + 1];
            for (int p = s; p < e; p++) {
                float4 pt = g_pts[p];
                float  D  = fmaf(qz, pt.z, fmaf(qy, pt.y, __fmul_rn(qx, pt.x)));
                float  d2 = __fsub_rn(__fadd_rn(A, pt.w), __fmul_rn(2.0f, D));
                if (d2 < worst) {
                    int jj = g_pidx[p];
#pragma unroll
                    for (int t = 0; t < KK; t++)
                        if (t == wpos) { bd[t] = d2; bi[t] = jj; }
                    worst = bd[0]; wpos = 0;
#pragma unroll
                    for (int t = 1; t < KK; t++)
                        if (bd[t] > worst) { worst = bd[t]; wpos = t; }
                }
            }
        }

        // coverage: distance from q to nearest unscanned region (scaled units);
        // faces clamped at the domain boundary are fully covered.
        float cov = 1e30f;
        if (nx0 > 0)       cov = fminf(cov, qx - (float)nx0 * 4.0f);
        if (nx1 < NC1 - 1) cov = fminf(cov, (float)(nx1 + 1) * 4.0f - qx);
        if (ny0 > 0)       cov = fminf(cov, qy - (float)ny0 * 4.0f);
        if (ny1 < NC1 - 1) cov = fminf(cov, (float)(ny1 + 1) * 4.0f - qy);
        if (nz0 > 0)       cov = fminf(cov, qz - (float)nz0 * 4.0f);
        if (nz1 < NC1 - 1) cov = fminf(cov, (float)(nz1 + 1) * 4.0f - qz);
        if (worst <= cov * cov * 0.999f) break;

        px0 = nx0; px1 = nx1; py0 = ny0; py1 = ny1; pz0 = nz0; pz1 = nz1;
    }

    // ---- canonicalize: sort 16 by (d2, idx) ascending (odd-even network,
    // compile-time indices -> registers). Matches top_k's output order. ----
    unsigned long long kkey[KK];
#pragma unroll
    for (int t = 0; t < KK; t++)
        kkey[t] = ((unsigned long long)f2ord(bd[t]) << 32) | (unsigned int)bi[t];
#pragma unroll
    for (int rd = 0; rd < KK; rd++) {
#pragma unroll
        for (int t = (rd & 1); t + 1 < KK; t += 2) {
            if (kkey[t] > kkey[t + 1]) {
                unsigned long long tmp = kkey[t]; kkey[t] = kkey[t + 1]; kkey[t + 1] = tmp;
            }
        }
    }
#pragma unroll
    for (int t = 0; t < KK; t++)
        g_knn[m * KK + t] = (int)(kkey[t] & 0xffffffffu);
}

// ---------------------------------------------------------------------------
// Kernel 2 (UNCHANGED, verified @237us): gather + edge MLP -> mean -> edge L2
// -> concat grid_feat -> out MLP. One warp per vertex.
// ---------------------------------------------------------------------------
__global__ __launch_bounds__(256) void mlp_kernel(
    const float* __restrict__ verts, const float* __restrict__ feats,
    const float* __restrict__ gverts, const float* __restrict__ gfeat,
    const float* __restrict__ ew1, const float* __restrict__ eb1,
    const float* __restrict__ eg1, const float* __restrict__ ebt1,
    const float* __restrict__ ew2, const float* __restrict__ eb2,
    const float* __restrict__ ow1, const float* __restrict__ ob1,
    const float* __restrict__ og1, const float* __restrict__ obt1,
    const float* __restrict__ ow2, const float* __restrict__ ob2,
    float* __restrict__ out)
{
    __shared__ float s_w1[EIN * CO];
    __shared__ float s_w2[CO * CO];
    __shared__ __align__(16) float s_et[8][EIN + 1][KK];
    __shared__ float s_buf[8][CO];

    const int tid = threadIdx.x;
    for (int i = tid; i < EIN * CO; i += 256) s_w1[i] = ew1[i];
    for (int i = tid; i < CO * CO; i += 256) s_w2[i] = ew2[i];

    const int w    = tid >> 5;
    const int lane = tid & 31;
    const int m    = blockIdx.x * 8 + w;
    const int c0   = lane * 2;

    const float2 p_eb1  = *(const float2*)(eb1  + c0);
    const float2 p_eg1  = *(const float2*)(eg1  + c0);
    const float2 p_ebt1 = *(const float2*)(ebt1 + c0);
    const float2 p_eb2  = *(const float2*)(eb2  + c0);
    const float2 p_ob1  = *(const float2*)(ob1  + c0);
    const float2 p_og1  = *(const float2*)(og1  + c0);
    const float2 p_obt1 = *(const float2*)(obt1 + c0);
    const float2 p_ob2  = *(const float2*)(ob2  + c0);

    {
        const int row  = lane >> 1;
        const int half = lane & 1;
        const int idx  = g_knn[m * KK + row];
        const float4* f4 = (const float4*)(feats + idx * CIN + half * 16);
        float4 a = f4[0], b = f4[1], c = f4[2], d = f4[3];
        const int ib = half * 16;
        float vals[16] = {a.x, a.y, a.z, a.w, b.x, b.y, b.z, b.w,
                          c.x, c.y, c.z, c.w, d.x, d.y, d.z, d.w};
#pragma unroll
        for (int t = 0; t < 16; t++) s_et[w][ib + t][row] = vals[t];
        if (half == 0) {
            s_et[w][32][row] = verts[idx * 3 + 0] - gverts[m * 3 + 0];
            s_et[w][33][row] = verts[idx * 3 + 1] - gverts[m * 3 + 1];
            s_et[w][34][row] = verts[idx * 3 + 2] - gverts[m * 3 + 2];
        }
    }
    __syncthreads();

    float gb0 = 0.0f, gb1 = 0.0f;
#pragma unroll
    for (int pass = 0; pass < 2; pass++) {
        const int r0 = pass * 8;
        float acc0[8], acc1[8];
#pragma unroll
        for (int r = 0; r < 8; r++) { acc0[r] = p_eb1.x; acc1[r] = p_eb1.y; }
#pragma unroll
        for (int i = 0; i < EIN; i++) {
            float4 e0 = *(const float4*)&s_et[w][i][r0];
            float4 e1 = *(const float4*)&s_et[w][i][r0 + 4];
            float2 wv = *(const float2*)&s_w1[i * CO + c0];
            acc0[0] = fmaf(e0.x, wv.x, acc0[0]); acc1[0] = fmaf(e0.x, wv.y, acc1[0]);
            acc0[1] = fmaf(e0.y, wv.x, acc0[1]); acc1[1] = fmaf(e0.y, wv.y, acc1[1]);
            acc0[2] = fmaf(e0.z, wv.x, acc0[2]); acc1[2] = fmaf(e0.z, wv.y, acc1[2]);
            acc0[3] = fmaf(e0.w, wv.x, acc0[3]); acc1[3] = fmaf(e0.w, wv.y, acc1[3]);
            acc0[4] = fmaf(e1.x, wv.x, acc0[4]); acc1[4] = fmaf(e1.x, wv.y, acc1[4]);
            acc0[5] = fmaf(e1.y, wv.x, acc0[5]); acc1[5] = fmaf(e1.y, wv.y, acc1[5]);
            acc0[6] = fmaf(e1.z, wv.x, acc0[6]); acc1[6] = fmaf(e1.z, wv.y, acc1[6]);
            acc0[7] = fmaf(e1.w, wv.x, acc0[7]); acc1[7] = fmaf(e1.w, wv.y, acc1[7]);
        }
#pragma unroll
        for (int r = 0; r < 8; r++) {
            float a0 = acc0[r], a1 = acc1[r];
            float s  = a0 + a1;
            float ss = fmaf(a0, a0, a1 * a1);
#pragma unroll
            for (int o = 16; o > 0; o >>= 1) {
                s  += __shfl_xor_sync(0xffffffffu, s,  o);
                ss += __shfl_xor_sync(0xffffffffu, ss, o);
            }
            float mean = s * (1.0f / 64.0f);
            float var  = ss * (1.0f / 64.0f) - mean * mean;
            float rstd = rsqrtf(var + 1e-5f);
            float h0 = fmaf((a0 - mean) * rstd, p_eg1.x, p_ebt1.x);
            float h1 = fmaf((a1 - mean) * rstd, p_eg1.y, p_ebt1.y);
            gb0 += gelu_tanh(h0);
            gb1 += gelu_tanh(h1);
        }
    }
    gb0 *= (1.0f / 16.0f);
    gb1 *= (1.0f / 16.0f);
    s_buf[w][c0] = gb0; s_buf[w][c0 + 1] = gb1;
    __syncwarp();

    float a0 = p_eb2.x, a1 = p_eb2.y;
#pragma unroll
    for (int i = 0; i < CO; i++) {
        float  g  = s_buf[w][i];
        float2 wv = *(const float2*)&s_w2[i * CO + c0];
        a0 = fmaf(g, wv.x, a0);
        a1 = fmaf(g, wv.y, a1);
    }
    __syncwarp();
    s_buf[w][c0] = a0; s_buf[w][c0 + 1] = a1;
    __syncwarp();

    float o0 = p_ob1.x, o1 = p_ob1.y;
#pragma unroll
    for (int i = 0; i < CO; i++) {
        float  g  = s_buf[w][i];
        float2 wv = __ldg((const float2*)(ow1 + i * CO + c0));
        o0 = fmaf(g, wv.x, o0);
        o1 = fmaf(g, wv.y, o1);
    }
    const float* gf = gfeat + m * 96;
#pragma unroll 8
    for (int i = 0; i < 96; i++) {
        float  g  = __ldg(gf + i);
        float2 wv = __ldg((const float2*)(ow1 + (CO + i) * CO + c0));
        o0 = fmaf(g, wv.x, o0);
        o1 = fmaf(g, wv.y, o1);
    }
    {
        float s  = o0 + o1;
        float ss = fmaf(o0, o0, o1 * o1);
#pragma unroll
        for (int o = 16; o > 0; o >>= 1) {
            s  += __shfl_xor_sync(0xffffffffu, s,  o);
            ss += __shfl_xor_sync(0xffffffffu, ss, o);
        }
        float mean = s * (1.0f / 64.0f);
        float var  = ss * (1.0f / 64.0f) - mean * mean;
        float rstd = rsqrtf(var + 1e-5f);
        o0 = gelu_tanh(fmaf((o0 - mean) * rstd, p_og1.x, p_obt1.x));
        o1 = gelu_tanh(fmaf((o1 - mean) * rstd, p_og1.y, p_obt1.y));
    }
    __syncwarp();
    s_buf[w][c0] = o0; s_buf[w][c0 + 1] = o1;
    __syncwarp();

    float f0 = p_ob2.x, f1 = p_ob2.y;
#pragma unroll
    for (int i = 0; i < CO; i++) {
        float  g  = s_buf[w][i];
        float2 wv = __ldg((const float2*)(ow2 + i * CO + c0));
        f0 = fmaf(g, wv.x, f0);
        f1 = fmaf(g, wv.y, f1);
    }
    *(float2*)(out + m * CO + c0) = make_float2(f0, f1);
}

// ---------------------------------------------------------------------------
extern "C" void kernel_launch(void* const* d_in, const int* in_sizes, int n_in,
                              void* d_out, int out_size) {
    const float* vertices = (const float*)d_in[0];
    const float* features = (const float*)d_in[1];
    const float* gverts   = (const float*)d_in[2];
    const float* gfeat    = (const float*)d_in[3];
    const float* ew1  = (const float*)d_in[4];
    const float* eb1  = (const float*)d_in[5];
    const float* eg1  = (const float*)d_in[6];
    const float* ebt1 = (const float*)d_in[7];
    const float* ew2  = (const float*)d_in[8];
    const float* eb2  = (const float*)d_in[9];
    const float* ow1  = (const float*)d_in[10];
    const float* ob1  = (const float*)d_in[11];
    const float* og1  = (const float*)d_in[12];
    const float* obt1 = (const float*)d_in[13];
    const float* ow2  = (const float*)d_in[14];
    const float* ob2  = (const float*)d_in[15];
    float* out = (float*)d_out;

    zero_kernel<<<1, NCELLS>>>();
    hist_kernel<<<N_PTS / 256, 256>>>(vertices);
    scan_kernel<<<1, NCELLS>>>();
    scatter_kernel<<<N_PTS / 256, 256>>>(vertices);
    knn_kernel<<<dim3(8, 8, 8), dim3(4, 4, 4)>>>(gverts);
    mlp_kernel<<<M_TOT / 8, 256>>>(vertices, features, gverts, gfeat,
                                   ew1, eb1, eg1, ebt1, ew2, eb2,
                                   ow1, ob1, og1, obt1, ow2, ob2, out);
}

// round 10
// speedup vs baseline: 4.5139x; 1.1955x over previous
#include <cuda_runtime.h>
#include <math.h>

#define M_TOT 32768
#define N_PTS 8192
#define KK    16
#define CIN   32
#define CO    64
#define EIN   35
#define NC1   8
#define NCELLS 512

// scratch (all __device__, no allocs)
__device__ int    g_cellid[N_PTS];
__device__ int    g_cnt[NCELLS];
__device__ int    g_off[NCELLS + 1];
__device__ float4 g_pts[N_PTS];
__device__ int    g_pidx[N_PTS];
__device__ int    g_knn[M_TOT * KK];
__device__ float  g_gmean[M_TOT * CO];   // 8 MB: post-gelu K-mean

__device__ __forceinline__ float gelu_tanh(float x) {
    float x3 = x * x * x;
    float t  = tanhf(0.7978845608028654f * (x + 0.044715f * x3));
    return 0.5f * x * (1.0f + t);
}

// order-preserving float <-> uint32
__device__ __forceinline__ unsigned int f2ord(float f) {
    unsigned int u = __float_as_uint(f);
    return (u & 0x80000000u) ? ~u : (u | 0x80000000u);
}
__device__ __forceinline__ float ord2f(unsigned int o) {
    unsigned int u = (o & 0x80000000u) ? (o & 0x7fffffffu) : ~o;
    return __uint_as_float(u);
}

// ---------------------------------------------------------------------------
// Binning pipeline: zero -> histogram -> scan -> scatter
// ---------------------------------------------------------------------------
__global__ void zero_kernel() { g_cnt[threadIdx.x] = 0; }

__global__ void hist_kernel(const float* __restrict__ verts) {
    int i = blockIdx.x * 256 + threadIdx.x;
    float rx = __fmul_rn(verts[i * 3 + 0], 32.0f);
    float ry = __fmul_rn(verts[i * 3 + 1], 32.0f);
    float rz = __fmul_rn(verts[i * 3 + 2], 32.0f);
    int cx = min(NC1 - 1, max(0, (int)(rx * 0.25f)));
    int cy = min(NC1 - 1, max(0, (int)(ry * 0.25f)));
    int cz = min(NC1 - 1, max(0, (int)(rz * 0.25f)));
    int c  = (cx * NC1 + cy) * NC1 + cz;
    g_cellid[i] = c;
    atomicAdd(&g_cnt[c], 1);
}

__global__ void scan_kernel() {
    __shared__ int s[NCELLS];
    int t = threadIdx.x;
    s[t] = g_cnt[t];
    __syncthreads();
    for (int o = 1; o < NCELLS; o <<= 1) {
        int x = (t >= o) ? s[t - o] : 0;
        __syncthreads();
        s[t] += x;
        __syncthreads();
    }
    g_off[t + 1] = s[t];
    if (t == 0) g_off[0] = 0;
    g_cnt[t] = 0;
}

__global__ void scatter_kernel(const float* __restrict__ verts) {
    int i = blockIdx.x * 256 + threadIdx.x;
    float rx = __fmul_rn(verts[i * 3 + 0], 32.0f);
    float ry = __fmul_rn(verts[i * 3 + 1], 32.0f);
    float rz = __fmul_rn(verts[i * 3 + 2], 32.0f);
    float B  = __fadd_rn(__fadd_rn(__fmul_rn(rx, rx), __fmul_rn(ry, ry)),
                         __fmul_rn(rz, rz));
    int c   = g_cellid[i];
    int pos = g_off[c] + atomicAdd(&g_cnt[c], 1);
    g_pts[pos]  = make_float4(rx, ry, rz, B);
    g_pidx[pos] = i;
}

// ---------------------------------------------------------------------------
// KNN with ring expansion. Selection uses LEXICOGRAPHIC (d2, idx) keys so the
// chosen set matches jax.lax.top_k exactly (lower index wins ties) and is
// independent of scan order / scatter nondeterminism. Ring termination keeps
// a 1e-3 absolute margin against fp noise in the expanded-form distance.
// ---------------------------------------------------------------------------
__global__ __launch_bounds__(64) void knn_kernel(const float* __restrict__ gverts) {
    const int ix = blockIdx.x * 4 + threadIdx.x;
    const int iy = blockIdx.y * 4 + threadIdx.y;
    const int iz = blockIdx.z * 4 + threadIdx.z;
    const int m  = (ix * 32 + iy) * 32 + iz;

    const float qx = __fmul_rn(gverts[m * 3 + 0], 32.0f);
    const float qy = __fmul_rn(gverts[m * 3 + 1], 32.0f);
    const float qz = __fmul_rn(gverts[m * 3 + 2], 32.0f);
    const float A  = __fadd_rn(__fadd_rn(__fmul_rn(qx, qx), __fmul_rn(qy, qy)),
                               __fmul_rn(qz, qz));

    const int cx = min(NC1 - 1, max(0, (int)(qx * 0.25f)));
    const int cy = min(NC1 - 1, max(0, (int)(qy * 0.25f)));
    const int cz = min(NC1 - 1, max(0, (int)(qz * 0.25f)));

    // sentinel decodes back to 3e38 (NOT all-ones, which would decode to NaN)
    const unsigned long long SENT =
        ((unsigned long long)f2ord(3.0e38f) << 32) | 0xffffffffull;
    unsigned long long kkey[KK];
#pragma unroll
    for (int t = 0; t < KK; t++) kkey[t] = SENT;
    unsigned long long worstkey = SENT;
    float worstf = 3.0e38f;
    int   wpos   = 0;

    int px0 = 1, px1 = 0, py0 = 1, py1 = 0, pz0 = 1, pz1 = 0;

    for (int r = 1; r <= NC1; r++) {
        const int nx0 = max(cx - r, 0), nx1 = min(cx + r, NC1 - 1);
        const int ny0 = max(cy - r, 0), ny1 = min(cy + r, NC1 - 1);
        const int nz0 = max(cz - r, 0), nz1 = min(cz + r, NC1 - 1);

        for (int x = nx0; x <= nx1; x++)
        for (int y = ny0; y <= ny1; y++)
        for (int z = nz0; z <= nz1; z++) {
            if (x >= px0 && x <= px1 && y >= py0 && y <= py1 &&
                z >= pz0 && z <= pz1) continue;
            const int c = (x * NC1 + y) * NC1 + z;
            const int s = g_off[c], e = g_off[c + 1];
            for (int p = s; p < e; p++) {
                float4 pt = g_pts[p];
                float  D  = fmaf(qz, pt.z, fmaf(qy, pt.y, __fmul_rn(qx, pt.x)));
                float  d2 = __fsub_rn(__fadd_rn(A, pt.w), __fmul_rn(2.0f, D));
                if (d2 <= worstf) {
                    unsigned long long key =
                        ((unsigned long long)f2ord(d2) << 32) |
                        (unsigned int)g_pidx[p];
                    if (key < worstkey) {
#pragma unroll
                        for (int t = 0; t < KK; t++)
                            if (t == wpos) kkey[t] = key;
                        worstkey = kkey[0]; wpos = 0;
#pragma unroll
                        for (int t = 1; t < KK; t++)
                            if (kkey[t] > worstkey) { worstkey = kkey[t]; wpos = t; }
                        worstf = ord2f((unsigned int)(worstkey >> 32));
                    }
                }
            }
        }

        float cov = 1e30f;
        if (nx0 > 0)       cov = fminf(cov, qx - (float)nx0 * 4.0f);
        if (nx1 < NC1 - 1) cov = fminf(cov, (float)(nx1 + 1) * 4.0f - qx);
        if (ny0 > 0)       cov = fminf(cov, qy - (float)ny0 * 4.0f);
        if (ny1 < NC1 - 1) cov = fminf(cov, (float)(ny1 + 1) * 4.0f - qy);
        if (nz0 > 0)       cov = fminf(cov, qz - (float)nz0 * 4.0f);
        if (nz1 < NC1 - 1) cov = fminf(cov, (float)(nz1 + 1) * 4.0f - qz);
        if (worstf <= cov * cov * 0.999f - 1e-3f) break;

        px0 = nx0; px1 = nx1; py0 = ny0; py1 = ny1; pz0 = nz0; pz1 = nz1;
    }

    // canonical order = ascending (d2, idx) = top_k order
#pragma unroll
    for (int rd = 0; rd < KK; rd++) {
#pragma unroll
        for (int t = (rd & 1); t + 1 < KK; t += 2) {
            if (kkey[t] > kkey[t + 1]) {
                unsigned long long tmp = kkey[t]; kkey[t] = kkey[t + 1]; kkey[t + 1] = tmp;
            }
        }
    }
#pragma unroll
    for (int t = 0; t < KK; t++)
        g_knn[m * KK + t] = (int)(kkey[t] & 0xffffffffu);
}

// ---------------------------------------------------------------------------
// Edge kernel: gather + edge L1 + LN + GELU + K-mean -> g_gmean.
// (verbatim measured-good path, out-MLP stage removed)
// ---------------------------------------------------------------------------
__global__ __launch_bounds__(256) void edge_kernel(
    const float* __restrict__ verts, const float* __restrict__ feats,
    const float* __restrict__ gverts,
    const float* __restrict__ ew1, const float* __restrict__ eb1,
    const float* __restrict__ eg1, const float* __restrict__ ebt1)
{
    __shared__ float s_w1[EIN * CO];
    __shared__ __align__(16) float s_et[8][EIN + 1][KK];

    const int tid = threadIdx.x;
    for (int i = tid; i < EIN * CO; i += 256) s_w1[i] = ew1[i];

    const int w    = tid >> 5;
    const int lane = tid & 31;
    const int m    = blockIdx.x * 8 + w;
    const int c0   = lane * 2;

    const float2 p_eb1  = *(const float2*)(eb1  + c0);
    const float2 p_eg1  = *(const float2*)(eg1  + c0);
    const float2 p_ebt1 = *(const float2*)(ebt1 + c0);

    {
        const int row  = lane >> 1;
        const int half = lane & 1;
        const int idx  = g_knn[m * KK + row];
        const float4* f4 = (const float4*)(feats + idx * CIN + half * 16);
        float4 a = f4[0], b = f4[1], c = f4[2], d = f4[3];
        const int ib = half * 16;
        float vals[16] = {a.x, a.y, a.z, a.w, b.x, b.y, b.z, b.w,
                          c.x, c.y, c.z, c.w, d.x, d.y, d.z, d.w};
#pragma unroll
        for (int t = 0; t < 16; t++) s_et[w][ib + t][row] = vals[t];
        if (half == 0) {
            s_et[w][32][row] = verts[idx * 3 + 0] - gverts[m * 3 + 0];
            s_et[w][33][row] = verts[idx * 3 + 1] - gverts[m * 3 + 1];
            s_et[w][34][row] = verts[idx * 3 + 2] - gverts[m * 3 + 2];
        }
    }
    __syncthreads();

    float gb0 = 0.0f, gb1 = 0.0f;
#pragma unroll
    for (int pass = 0; pass < 2; pass++) {
        const int r0 = pass * 8;
        float acc0[8], acc1[8];
#pragma unroll
        for (int r = 0; r < 8; r++) { acc0[r] = p_eb1.x; acc1[r] = p_eb1.y; }
#pragma unroll
        for (int i = 0; i < EIN; i++) {
            float4 e0 = *(const float4*)&s_et[w][i][r0];
            float4 e1 = *(const float4*)&s_et[w][i][r0 + 4];
            float2 wv = *(const float2*)&s_w1[i * CO + c0];
            acc0[0] = fmaf(e0.x, wv.x, acc0[0]); acc1[0] = fmaf(e0.x, wv.y, acc1[0]);
            acc0[1] = fmaf(e0.y, wv.x, acc0[1]); acc1[1] = fmaf(e0.y, wv.y, acc1[1]);
            acc0[2] = fmaf(e0.z, wv.x, acc0[2]); acc1[2] = fmaf(e0.z, wv.y, acc1[2]);
            acc0[3] = fmaf(e0.w, wv.x, acc0[3]); acc1[3] = fmaf(e0.w, wv.y, acc1[3]);
            acc0[4] = fmaf(e1.x, wv.x, acc0[4]); acc1[4] = fmaf(e1.x, wv.y, acc1[4]);
            acc0[5] = fmaf(e1.y, wv.x, acc0[5]); acc1[5] = fmaf(e1.y, wv.y, acc1[5]);
            acc0[6] = fmaf(e1.z, wv.x, acc0[6]); acc1[6] = fmaf(e1.z, wv.y, acc1[6]);
            acc0[7] = fmaf(e1.w, wv.x, acc0[7]); acc1[7] = fmaf(e1.w, wv.y, acc1[7]);
        }
#pragma unroll
        for (int r = 0; r < 8; r++) {
            float a0 = acc0[r], a1 = acc1[r];
            float s  = a0 + a1;
            float ss = fmaf(a0, a0, a1 * a1);
#pragma unroll
            for (int o = 16; o > 0; o >>= 1) {
                s  += __shfl_xor_sync(0xffffffffu, s,  o);
                ss += __shfl_xor_sync(0xffffffffu, ss, o);
            }
            float mean = s * (1.0f / 64.0f);
            float var  = ss * (1.0f / 64.0f) - mean * mean;
            float rstd = rsqrtf(var + 1e-5f);
            float h0 = fmaf((a0 - mean) * rstd, p_eg1.x, p_ebt1.x);
            float h1 = fmaf((a1 - mean) * rstd, p_eg1.y, p_ebt1.y);
            gb0 += gelu_tanh(h0);
            gb1 += gelu_tanh(h1);
        }
    }
    gb0 *= (1.0f / 16.0f);
    gb1 *= (1.0f / 16.0f);
    *(float2*)(g_gmean + m * CO + c0) = make_float2(gb0, gb1);
}

// ---------------------------------------------------------------------------
// Out kernel: agg2 = gmean@ew2+eb2; o = concat(agg2, gfeat)@ow1+ob1;
// out = gelu(LN(o))@ow2+ob2. Warp handles 4 vertices (register blocking):
// each weight fetch feeds 8 FMAs -> 4x less weight traffic per vertex.
// ---------------------------------------------------------------------------
__global__ __launch_bounds__(256) void out_kernel(
    const float* __restrict__ gfeat,
    const float* __restrict__ ew2, const float* __restrict__ eb2,
    const float* __restrict__ ow1, const float* __restrict__ ob1,
    const float* __restrict__ og1, const float* __restrict__ obt1,
    const float* __restrict__ ow2, const float* __restrict__ ob2,
    float* __restrict__ out)
{
    __shared__ __align__(16) float4 s_x[8][160];   // 20.5 KB

    const int tid  = threadIdx.x;
    const int w    = tid >> 5;
    const int lane = tid & 31;
    const int c0   = lane * 2;
    const int v0   = blockIdx.x * 32 + w * 4;

    // load gmean (rows 0..63) and gfeat (rows 64..159), 4-vertex transposed
    for (int i = lane; i < CO; i += 32)
        s_x[w][i] = make_float4(g_gmean[(v0 + 0) * CO + i], g_gmean[(v0 + 1) * CO + i],
                                g_gmean[(v0 + 2) * CO + i], g_gmean[(v0 + 3) * CO + i]);
    for (int i = lane; i < 96; i += 32)
        s_x[w][CO + i] = make_float4(gfeat[(v0 + 0) * 96 + i], gfeat[(v0 + 1) * 96 + i],
                                     gfeat[(v0 + 2) * 96 + i], gfeat[(v0 + 3) * 96 + i]);
    __syncwarp();

    // ---- stage A: agg2 = gmean @ ew2 + eb2 ----
    const float2 p_eb2 = *(const float2*)(eb2 + c0);
    float a00 = p_eb2.x, a01 = p_eb2.y, a10 = p_eb2.x, a11 = p_eb2.y;
    float a20 = p_eb2.x, a21 = p_eb2.y, a30 = p_eb2.x, a31 = p_eb2.y;
#pragma unroll 8
    for (int i = 0; i < CO; i++) {
        float4 x = s_x[w][i];
        float2 u = __ldg((const float2*)(ew2 + i * CO + c0));
        a00 = fmaf(x.x, u.x, a00); a01 = fmaf(x.x, u.y, a01);
        a10 = fmaf(x.y, u.x, a10); a11 = fmaf(x.y, u.y, a11);
        a20 = fmaf(x.z, u.x, a20); a21 = fmaf(x.z, u.y, a21);
        a30 = fmaf(x.w, u.x, a30); a31 = fmaf(x.w, u.y, a31);
    }
    __syncwarp();
    // transpose agg2 back into rows 0..63 (each lane writes its 2 channels)
    s_x[w][c0]     = make_float4(a00, a10, a20, a30);
    s_x[w][c0 + 1] = make_float4(a01, a11, a21, a31);
    __syncwarp();

    // ---- stage B: o = concat @ ow1 + ob1 ----
    const float2 p_ob1 = *(const float2*)(ob1 + c0);
    float o00 = p_ob1.x, o01 = p_ob1.y, o10 = p_ob1.x, o11 = p_ob1.y;
    float o20 = p_ob1.x, o21 = p_ob1.y, o30 = p_ob1.x, o31 = p_ob1.y;
#pragma unroll 8
    for (int i = 0; i < CO + 96; i++) {
        float4 x = s_x[w][i];
        float2 u = __ldg((const float2*)(ow1 + i * CO + c0));
        o00 = fmaf(x.x, u.x, o00); o01 = fmaf(x.x, u.y, o01);
        o10 = fmaf(x.y, u.x, o10); o11 = fmaf(x.y, u.y, o11);
        o20 = fmaf(x.z, u.x, o20); o21 = fmaf(x.z, u.y, o21);
        o30 = fmaf(x.w, u.x, o30); o31 = fmaf(x.w, u.y, o31);
    }

    // ---- LN + GELU per vertex ----
    const float2 p_og1  = *(const float2*)(og1  + c0);
    const float2 p_obt1 = *(const float2*)(obt1 + c0);
    float g0[4], g1[4];
    float ov0[4] = {o00, o10, o20, o30};
    float ov1[4] = {o01, o11, o21, o31};
#pragma unroll
    for (int v = 0; v < 4; v++) {
        float b0 = ov0[v], b1 = ov1[v];
        float s  = b0 + b1;
        float ss = fmaf(b0, b0, b1 * b1);
#pragma unroll
        for (int o = 16; o > 0; o >>= 1) {
            s  += __shfl_xor_sync(0xffffffffu, s,  o);
            ss += __shfl_xor_sync(0xffffffffu, ss, o);
        }
        float mean = s * (1.0f / 64.0f);
        float var  = ss * (1.0f / 64.0f) - mean * mean;
        float rstd = rsqrtf(var + 1e-5f);
        g0[v] = gelu_tanh(fmaf((b0 - mean) * rstd, p_og1.x, p_obt1.x));
        g1[v] = gelu_tanh(fmaf((b1 - mean) * rstd, p_og1.y, p_obt1.y));
    }
    __syncwarp();
    s_x[w][c0]     = make_float4(g0[0], g0[1], g0[2], g0[3]);
    s_x[w][c0 + 1] = make_float4(g1[0], g1[1], g1[2], g1[3]);
    __syncwarp();

    // ---- stage C: out = g @ ow2 + ob2 ----
    const float2 p_ob2 = *(const float2*)(ob2 + c0);
    float f00 = p_ob2.x, f01 = p_ob2.y, f10 = p_ob2.x, f11 = p_ob2.y;
    float f20 = p_ob2.x, f21 = p_ob2.y, f30 = p_ob2.x, f31 = p_ob2.y;
#pragma unroll 8
    for (int j = 0; j < CO; j++) {
        float4 x = s_x[w][j];
        float2 u = __ldg((const float2*)(ow2 + j * CO + c0));
        f00 = fmaf(x.x, u.x, f00); f01 = fmaf(x.x, u.y, f01);
        f10 = fmaf(x.y, u.x, f10); f11 = fmaf(x.y, u.y, f11);
        f20 = fmaf(x.z, u.x, f20); f21 = fmaf(x.z, u.y, f21);
        f30 = fmaf(x.w, u.x, f30); f31 = fmaf(x.w, u.y, f31);
    }
    *(float2*)(out + (v0 + 0) * CO + c0) = make_float2(f00, f01);
    *(float2*)(out + (v0 + 1) * CO + c0) = make_float2(f10, f11);
    *(float2*)(out + (v0 + 2) * CO + c0) = make_float2(f20, f21);
    *(float2*)(out + (v0 + 3) * CO + c0) = make_float2(f30, f31);
}

// ---------------------------------------------------------------------------
extern "C" void kernel_launch(void* const* d_in, const int* in_sizes, int n_in,
                              void* d_out, int out_size) {
    const float* vertices = (const float*)d_in[0];
    const float* features = (const float*)d_in[1];
    const float* gverts   = (const float*)d_in[2];
    const float* gfeat    = (const float*)d_in[3];
    const float* ew1  = (const float*)d_in[4];
    const float* eb1  = (const float*)d_in[5];
    const float* eg1  = (const float*)d_in[6];
    const float* ebt1 = (const float*)d_in[7];
    const float* ew2  = (const float*)d_in[8];
    const float* eb2  = (const float*)d_in[9];
    const float* ow1  = (const float*)d_in[10];
    const float* ob1  = (const float*)d_in[11];
    const float* og1  = (const float*)d_in[12];
    const float* obt1 = (const float*)d_in[13];
    const float* ow2  = (const float*)d_in[14];
    const float* ob2  = (const float*)d_in[15];
    float* out = (float*)d_out;

    zero_kernel<<<1, NCELLS>>>();
    hist_kernel<<<N_PTS / 256, 256>>>(vertices);
    scan_kernel<<<1, NCELLS>>>();
    scatter_kernel<<<N_PTS / 256, 256>>>(vertices);
    knn_kernel<<<dim3(8, 8, 8), dim3(4, 4, 4)>>>(gverts);
    edge_kernel<<<M_TOT / 8, 256>>>(vertices, features, gverts,
                                    ew1, eb1, eg1, ebt1);
    out_kernel<<<M_TOT / 32, 256>>>(gfeat, ew2, eb2, ow1, ob1,
                                    og1, obt1, ow2, ob2, out);
}

// round 12
// speedup vs baseline: 5.5688x; 1.2337x over previous
#include <cuda_runtime.h>
#include <math.h>

#define M_TOT 32768
#define N_PTS 8192
#define KK    16
#define CIN   32
#define CO    64
#define NC1   8
#define NCELLS 512

// scratch (all __device__, no allocs)
__device__ int    g_cellid[N_PTS];
__device__ int    g_off[NCELLS + 1];
__device__ float4 g_pts[N_PTS];
__device__ int    g_pidx[N_PTS];
__device__ int    g_knn[M_TOT * KK];
__device__ float  g_gmean[M_TOT * CO];   // 8 MB: post-gelu K-mean
__device__ float  g_P[N_PTS * CO];       // 2 MB: features @ ew1[0:32]

__device__ __forceinline__ float gelu_tanh(float x) {
    float x3  = x * x * x;
    float arg = 0.7978845608028654f * (x + 0.044715f * x3);
    float t;
    asm("tanh.approx.f32 %0, %1;" : "=f"(t) : "f"(arg));
    return 0.5f * x * (1.0f + t);
}

// order-preserving float <-> uint32
__device__ __forceinline__ unsigned int f2ord(float f) {
    unsigned int u = __float_as_uint(f);
    return (u & 0x80000000u) ? ~u : (u | 0x80000000u);
}
__device__ __forceinline__ float ord2f(unsigned int o) {
    unsigned int u = (o & 0x80000000u) ? (o & 0x7fffffffu) : ~o;
    return __uint_as_float(u);
}

// ---------------------------------------------------------------------------
// Fused binning: smem histogram -> smem scan -> scatter. One 512-thread block.
// ---------------------------------------------------------------------------
__global__ __launch_bounds__(NCELLS) void bin_kernel(const float* __restrict__ verts) {
    __shared__ int s_cnt[NCELLS];
    __shared__ int s_scan[NCELLS];
    const int t = threadIdx.x;
    s_cnt[t] = 0;
    __syncthreads();

    for (int i = t; i < N_PTS; i += NCELLS) {
        float rx = __fmul_rn(verts[i * 3 + 0], 32.0f);
        float ry = __fmul_rn(verts[i * 3 + 1], 32.0f);
        float rz = __fmul_rn(verts[i * 3 + 2], 32.0f);
        int cx = min(NC1 - 1, max(0, (int)(rx * 0.25f)));
        int cy = min(NC1 - 1, max(0, (int)(ry * 0.25f)));
        int cz = min(NC1 - 1, max(0, (int)(rz * 0.25f)));
        int c  = (cx * NC1 + cy) * NC1 + cz;
        g_cellid[i] = c;
        atomicAdd(&s_cnt[c], 1);
    }
    __syncthreads();

    int v = s_cnt[t];
    s_scan[t] = v;
    __syncthreads();
    for (int o = 1; o < NCELLS; o <<= 1) {
        int x = (t >= o) ? s_scan[t - o] : 0;
        __syncthreads();
        s_scan[t] += x;
        __syncthreads();
    }
    g_off[t + 1] = s_scan[t];
    if (t == 0) g_off[0] = 0;
    s_cnt[t] = s_scan[t] - v;   // exclusive offset = scatter cursor
    __syncthreads();

    for (int i = t; i < N_PTS; i += NCELLS) {
        float rx = __fmul_rn(verts[i * 3 + 0], 32.0f);
        float ry = __fmul_rn(verts[i * 3 + 1], 32.0f);
        float rz = __fmul_rn(verts[i * 3 + 2], 32.0f);
        float B  = __fadd_rn(__fadd_rn(__fmul_rn(rx, rx), __fmul_rn(ry, ry)),
                             __fmul_rn(rz, rz));
        int c   = g_cellid[i];
        int pos = atomicAdd(&s_cnt[c], 1);
        g_pts[pos]  = make_float4(rx, ry, rz, B);
        g_pidx[pos] = i;
    }
}

// ---------------------------------------------------------------------------
// Precompute P[n] = features[n] @ ew1[0:32]  (query-independent GEMM part).
// One warp per point, 2 channels per lane.
// ---------------------------------------------------------------------------
__global__ __launch_bounds__(256) void pre_kernel(const float* __restrict__ feats,
                                                  const float* __restrict__ ew1) {
    const int n    = (blockIdx.x * 256 + threadIdx.x) >> 5;
    const int lane = threadIdx.x & 31;
    const int c0   = lane * 2;
    const float* f = feats + n * CIN;
    float a0 = 0.0f, a1 = 0.0f;
#pragma unroll
    for (int i = 0; i < CIN; i++) {
        float  fv = __ldg(f + i);
        float2 u  = __ldg((const float2*)(ew1 + i * CO + c0));
        a0 = fmaf(fv, u.x, a0);
        a1 = fmaf(fv, u.y, a1);
    }
    *(float2*)(g_P + n * CO + c0) = make_float2(a0, a1);
}

// ---------------------------------------------------------------------------
// KNN (UNCHANGED, verified): ring expansion, lexicographic (d2, idx) keys.
// ---------------------------------------------------------------------------
__global__ __launch_bounds__(64) void knn_kernel(const float* __restrict__ gverts) {
    const int ix = blockIdx.x * 4 + threadIdx.x;
    const int iy = blockIdx.y * 4 + threadIdx.y;
    const int iz = blockIdx.z * 4 + threadIdx.z;
    const int m  = (ix * 32 + iy) * 32 + iz;

    const float qx = __fmul_rn(gverts[m * 3 + 0], 32.0f);
    const float qy = __fmul_rn(gverts[m * 3 + 1], 32.0f);
    const float qz = __fmul_rn(gverts[m * 3 + 2], 32.0f);
    const float A  = __fadd_rn(__fadd_rn(__fmul_rn(qx, qx), __fmul_rn(qy, qy)),
                               __fmul_rn(qz, qz));

    const int cx = min(NC1 - 1, max(0, (int)(qx * 0.25f)));
    const int cy = min(NC1 - 1, max(0, (int)(qy * 0.25f)));
    const int cz = min(NC1 - 1, max(0, (int)(qz * 0.25f)));

    const unsigned long long SENT =
        ((unsigned long long)f2ord(3.0e38f) << 32) | 0xffffffffull;
    unsigned long long kkey[KK];
#pragma unroll
    for (int t = 0; t < KK; t++) kkey[t] = SENT;
    unsigned long long worstkey = SENT;
    float worstf = 3.0e38f;
    int   wpos   = 0;

    int px0 = 1, px1 = 0, py0 = 1, py1 = 0, pz0 = 1, pz1 = 0;

    for (int r = 1; r <= NC1; r++) {
        const int nx0 = max(cx - r, 0), nx1 = min(cx + r, NC1 - 1);
        const int ny0 = max(cy - r, 0), ny1 = min(cy + r, NC1 - 1);
        const int nz0 = max(cz - r, 0), nz1 = min(cz + r, NC1 - 1);

        for (int x = nx0; x <= nx1; x++)
        for (int y = ny0; y <= ny1; y++)
        for (int z = nz0; z <= nz1; z++) {
            if (x >= px0 && x <= px1 && y >= py0 && y <= py1 &&
                z >= pz0 && z <= pz1) continue;
            const int c = (x * NC1 + y) * NC1 + z;
            const int s = g_off[c], e = g_off[c + 1];
            for (int p = s; p < e; p++) {
                float4 pt = g_pts[p];
                float  D  = fmaf(qz, pt.z, fmaf(qy, pt.y, __fmul_rn(qx, pt.x)));
                float  d2 = __fsub_rn(__fadd_rn(A, pt.w), __fmul_rn(2.0f, D));
                if (d2 <= worstf) {
                    unsigned long long key =
                        ((unsigned long long)f2ord(d2) << 32) |
                        (unsigned int)g_pidx[p];
                    if (key < worstkey) {
#pragma unroll
                        for (int t = 0; t < KK; t++)
                            if (t == wpos) kkey[t] = key;
                        worstkey = kkey[0]; wpos = 0;
#pragma unroll
                        for (int t = 1; t < KK; t++)
                            if (kkey[t] > worstkey) { worstkey = kkey[t]; wpos = t; }
                        worstf = ord2f((unsigned int)(worstkey >> 32));
                    }
                }
            }
        }

        float cov = 1e30f;
        if (nx0 > 0)       cov = fminf(cov, qx - (float)nx0 * 4.0f);
        if (nx1 < NC1 - 1) cov = fminf(cov, (float)(nx1 + 1) * 4.0f - qx);
        if (ny0 > 0)       cov = fminf(cov, qy - (float)ny0 * 4.0f);
        if (ny1 < NC1 - 1) cov = fminf(cov, (float)(ny1 + 1) * 4.0f - qy);
        if (nz0 > 0)       cov = fminf(cov, qz - (float)nz0 * 4.0f);
        if (nz1 < NC1 - 1) cov = fminf(cov, (float)(nz1 + 1) * 4.0f - qz);
        if (worstf <= cov * cov * 0.999f - 1e-3f) break;

        px0 = nx0; px1 = nx1; py0 = ny0; py1 = ny1; pz0 = nz0; pz1 = nz1;
    }

#pragma unroll
    for (int rd = 0; rd < KK; rd++) {
#pragma unroll
        for (int t = (rd & 1); t + 1 < KK; t += 2) {
            if (kkey[t] > kkey[t + 1]) {
                unsigned long long tmp = kkey[t]; kkey[t] = kkey[t + 1]; kkey[t + 1] = tmp;
            }
        }
    }
#pragma unroll
    for (int t = 0; t < KK; t++)
        g_knn[m * KK + t] = (int)(kkey[t] & 0xffffffffu);
}

// ---------------------------------------------------------------------------
// Edge kernel: acc = P[idx] + eb1 + rel_pos @ ew1[32:35]; LN; GELU; K-mean.
// One warp per vertex, 2 channels per lane. P-precompute removes 32/35 of
// the layer-1 GEMM; smem drops to ~2.5KB.
// ---------------------------------------------------------------------------
__global__ __launch_bounds__(256) void edge_kernel(
    const float* __restrict__ verts, const float* __restrict__ gverts,
    const float* __restrict__ ew1, const float* __restrict__ eb1,
    const float* __restrict__ eg1, const float* __restrict__ ebt1)
{
    __shared__ int   s_idx[8][KK];
    __shared__ float s_rp[8][KK][4];

    const int tid  = threadIdx.x;
    const int w    = tid >> 5;
    const int lane = tid & 31;
    const int m    = blockIdx.x * 8 + w;
    const int c0   = lane * 2;

    const float2 w32 = __ldg((const float2*)(ew1 + 32 * CO + c0));
    const float2 w33 = __ldg((const float2*)(ew1 + 33 * CO + c0));
    const float2 w34 = __ldg((const float2*)(ew1 + 34 * CO + c0));
    const float2 p_eb1  = *(const float2*)(eb1  + c0);
    const float2 p_eg1  = *(const float2*)(eg1  + c0);
    const float2 p_ebt1 = *(const float2*)(ebt1 + c0);

    if (lane < KK) {
        int idx = g_knn[m * KK + lane];
        s_idx[w][lane] = idx;
        s_rp[w][lane][0] = verts[idx * 3 + 0] - gverts[m * 3 + 0];
        s_rp[w][lane][1] = verts[idx * 3 + 1] - gverts[m * 3 + 1];
        s_rp[w][lane][2] = verts[idx * 3 + 2] - gverts[m * 3 + 2];
    }
    __syncwarp();

    float gb0 = 0.0f, gb1 = 0.0f;
#pragma unroll
    for (int pass = 0; pass < 2; pass++) {
        const int r0 = pass * 8;
        float acc0[8], acc1[8];
#pragma unroll
        for (int r = 0; r < 8; r++) {
            int    idx = s_idx[w][r0 + r];
            float2 p   = __ldg((const float2*)(g_P + idx * CO + c0));
            float  rx  = s_rp[w][r0 + r][0];
            float  ry  = s_rp[w][r0 + r][1];
            float  rz  = s_rp[w][r0 + r][2];
            float a0 = p.x + p_eb1.x;
            float a1 = p.y + p_eb1.y;
            a0 = fmaf(rx, w32.x, a0); a1 = fmaf(rx, w32.y, a1);
            a0 = fmaf(ry, w33.x, a0); a1 = fmaf(ry, w33.y, a1);
            a0 = fmaf(rz, w34.x, a0); a1 = fmaf(rz, w34.y, a1);
            acc0[r] = a0; acc1[r] = a1;
        }
#pragma unroll
        for (int r = 0; r < 8; r++) {
            float a0 = acc0[r], a1 = acc1[r];
            float s  = a0 + a1;
            float ss = fmaf(a0, a0, a1 * a1);
#pragma unroll
            for (int o = 16; o > 0; o >>= 1) {
                s  += __shfl_xor_sync(0xffffffffu, s,  o);
                ss += __shfl_xor_sync(0xffffffffu, ss, o);
            }
            float mean = s * (1.0f / 64.0f);
            float var  = ss * (1.0f / 64.0f) - mean * mean;
            float rstd = rsqrtf(var + 1e-5f);
            float h0 = fmaf((a0 - mean) * rstd, p_eg1.x, p_ebt1.x);
            float h1 = fmaf((a1 - mean) * rstd, p_eg1.y, p_ebt1.y);
            gb0 += gelu_tanh(h0);
            gb1 += gelu_tanh(h1);
        }
    }
    gb0 *= (1.0f / 16.0f);
    gb1 *= (1.0f / 16.0f);
    *(float2*)(g_gmean + m * CO + c0) = make_float2(gb0, gb1);
}

// ---------------------------------------------------------------------------
// Out kernel (UNCHANGED, verified): agg2 = gmean@ew2+eb2; concat gfeat;
// LN+GELU; @ow2. Warp handles 4 vertices.
// ---------------------------------------------------------------------------
__global__ __launch_bounds__(256) void out_kernel(
    const float* __restrict__ gfeat,
    const float* __restrict__ ew2, const float* __restrict__ eb2,
    const float* __restrict__ ow1, const float* __restrict__ ob1,
    const float* __restrict__ og1, const float* __restrict__ obt1,
    const float* __restrict__ ow2, const float* __restrict__ ob2,
    float* __restrict__ out)
{
    __shared__ __align__(16) float4 s_x[8][160];

    const int tid  = threadIdx.x;
    const int w    = tid >> 5;
    const int lane = tid & 31;
    const int c0   = lane * 2;
    const int v0   = blockIdx.x * 32 + w * 4;

    for (int i = lane; i < CO; i += 32)
        s_x[w][i] = make_float4(g_gmean[(v0 + 0) * CO + i], g_gmean[(v0 + 1) * CO + i],
                                g_gmean[(v0 + 2) * CO + i], g_gmean[(v0 + 3) * CO + i]);
    for (int i = lane; i < 96; i += 32)
        s_x[w][CO + i] = make_float4(gfeat[(v0 + 0) * 96 + i], gfeat[(v0 + 1) * 96 + i],
                                     gfeat[(v0 + 2) * 96 + i], gfeat[(v0 + 3) * 96 + i]);
    __syncwarp();

    const float2 p_eb2 = *(const float2*)(eb2 + c0);
    float a00 = p_eb2.x, a01 = p_eb2.y, a10 = p_eb2.x, a11 = p_eb2.y;
    float a20 = p_eb2.x, a21 = p_eb2.y, a30 = p_eb2.x, a31 = p_eb2.y;
#pragma unroll 8
    for (int i = 0; i < CO; i++) {
        float4 x = s_x[w][i];
        float2 u = __ldg((const float2*)(ew2 + i * CO + c0));
        a00 = fmaf(x.x, u.x, a00); a01 = fmaf(x.x, u.y, a01);
        a10 = fmaf(x.y, u.x, a10); a11 = fmaf(x.y, u.y, a11);
        a20 = fmaf(x.z, u.x, a20); a21 = fmaf(x.z, u.y, a21);
        a30 = fmaf(x.w, u.x, a30); a31 = fmaf(x.w, u.y, a31);
    }
    __syncwarp();
    s_x[w][c0]     = make_float4(a00, a10, a20, a30);
    s_x[w][c0 + 1] = make_float4(a01, a11, a21, a31);
    __syncwarp();

    const float2 p_ob1 = *(const float2*)(ob1 + c0);
    float o00 = p_ob1.x, o01 = p_ob1.y, o10 = p_ob1.x, o11 = p_ob1.y;
    float o20 = p_ob1.x, o21 = p_ob1.y, o30 = p_ob1.x, o31 = p_ob1.y;
#pragma unroll 8
    for (int i = 0; i < CO + 96; i++) {
        float4 x = s_x[w][i];
        float2 u = __ldg((const float2*)(ow1 + i * CO + c0));
        o00 = fmaf(x.x, u.x, o00); o01 = fmaf(x.x, u.y, o01);
        o10 = fmaf(x.y, u.x, o10); o11 = fmaf(x.y, u.y, o11);
        o20 = fmaf(x.z, u.x, o20); o21 = fmaf(x.z, u.y, o21);
        o30 = fmaf(x.w, u.x, o30); o31 = fmaf(x.w, u.y, o31);
    }

    const float2 p_og1  = *(const float2*)(og1  + c0);
    const float2 p_obt1 = *(const float2*)(obt1 + c0);
    float g0[4], g1[4];
    float ov0[4] = {o00, o10, o20, o30};
    float ov1[4] = {o01, o11, o21, o31};
#pragma unroll
    for (int v = 0; v < 4; v++) {
        float b0 = ov0[v], b1 = ov1[v];
        float s  = b0 + b1;
        float ss = fmaf(b0, b0, b1 * b1);
#pragma unroll
        for (int o = 16; o > 0; o >>= 1) {
            s  += __shfl_xor_sync(0xffffffffu, s,  o);
            ss += __shfl_xor_sync(0xffffffffu, ss, o);
        }
        float mean = s * (1.0f / 64.0f);
        float var  = ss * (1.0f / 64.0f) - mean * mean;
        float rstd = rsqrtf(var + 1e-5f);
        g0[v] = gelu_tanh(fmaf((b0 - mean) * rstd, p_og1.x, p_obt1.x));
        g1[v] = gelu_tanh(fmaf((b1 - mean) * rstd, p_og1.y, p_obt1.y));
    }
    __syncwarp();
    s_x[w][c0]     = make_float4(g0[0], g0[1], g0[2], g0[3]);
    s_x[w][c0 + 1] = make_float4(g1[0], g1[1], g1[2], g1[3]);
    __syncwarp();

    const float2 p_ob2 = *(const float2*)(ob2 + c0);
    float f00 = p_ob2.x, f01 = p_ob2.y, f10 = p_ob2.x, f11 = p_ob2.y;
    float f20 = p_ob2.x, f21 = p_ob2.y, f30 = p_ob2.x, f31 = p_ob2.y;
#pragma unroll 8
    for (int j = 0; j < CO; j++) {
        float4 x = s_x[w][j];
        float2 u = __ldg((const float2*)(ow2 + j * CO + c0));
        f00 = fmaf(x.x, u.x, f00); f01 = fmaf(x.x, u.y, f01);
        f10 = fmaf(x.y, u.x, f10); f11 = fmaf(x.y, u.y, f11);
        f20 = fmaf(x.z, u.x, f20); f21 = fmaf(x.z, u.y, f21);
        f30 = fmaf(x.w, u.x, f30); f31 = fmaf(x.w, u.y, f31);
    }
    *(float2*)(out + (v0 + 0) * CO + c0) = make_float2(f00, f01);
    *(float2*)(out + (v0 + 1) * CO + c0) = make_float2(f10, f11);
    *(float2*)(out + (v0 + 2) * CO + c0) = make_float2(f20, f21);
    *(float2*)(out + (v0 + 3) * CO + c0) = make_float2(f30, f31);
}

// ---------------------------------------------------------------------------
extern "C" void kernel_launch(void* const* d_in, const int* in_sizes, int n_in,
                              void* d_out, int out_size) {
    const float* vertices = (const float*)d_in[0];
    const float* features = (const float*)d_in[1];
    const float* gverts   = (const float*)d_in[2];
    const float* gfeat    = (const float*)d_in[3];
    const float* ew1  = (const float*)d_in[4];
    const float* eb1  = (const float*)d_in[5];
    const float* eg1  = (const float*)d_in[6];
    const float* ebt1 = (const float*)d_in[7];
    const float* ew2  = (const float*)d_in[8];
    const float* eb2  = (const float*)d_in[9];
    const float* ow1  = (const float*)d_in[10];
    const float* ob1  = (const float*)d_in[11];
    const float* og1  = (const float*)d_in[12];
    const float* obt1 = (const float*)d_in[13];
    const float* ow2  = (const float*)d_in[14];
    const float* ob2  = (const float*)d_in[15];
    float* out = (float*)d_out;

    bin_kernel<<<1, NCELLS>>>(vertices);
    pre_kernel<<<N_PTS * 32 / 256, 256>>>(features, ew1);
    knn_kernel<<<dim3(8, 8, 8), dim3(4, 4, 4)>>>(gverts);
    edge_kernel<<<M_TOT / 8, 256>>>(vertices, gverts, ew1, eb1, eg1, ebt1);
    out_kernel<<<M_TOT / 32, 256>>>(gfeat, ew2, eb2, ow1, ob1,
                                    og1, obt1, ow2, ob2, out);
}

// round 13
// speedup vs baseline: 6.3067x; 1.1325x over previous
#include <cuda_runtime.h>
#include <math.h>

#define M_TOT 32768
#define N_PTS 8192
#define KK    16
#define CIN   32
#define CO    64
#define NC1   8
#define NCELLS 512

// scratch (all __device__, no allocs)
__device__ int    g_cellid[N_PTS];
__device__ int    g_off[NCELLS + 1];
__device__ float4 g_pts[N_PTS];
__device__ int    g_pidx[N_PTS];
__device__ int    g_knn[M_TOT * KK];
__device__ float  g_gmean[M_TOT * CO];   // 8 MB: post-gelu K-mean
__device__ float  g_P[N_PTS * CO];       // 2 MB: features @ ew1[0:32]

// 27 neighbor offsets ordered near-to-far: home, 6 faces, 12 edges, 8 corners
__constant__ signed char c_off[27][3] = {
    { 0, 0, 0},
    {-1, 0, 0}, { 1, 0, 0}, { 0,-1, 0}, { 0, 1, 0}, { 0, 0,-1}, { 0, 0, 1},
    {-1,-1, 0}, {-1, 1, 0}, { 1,-1, 0}, { 1, 1, 0},
    {-1, 0,-1}, {-1, 0, 1}, { 1, 0,-1}, { 1, 0, 1},
    { 0,-1,-1}, { 0,-1, 1}, { 0, 1,-1}, { 0, 1, 1},
    {-1,-1,-1}, {-1,-1, 1}, {-1, 1,-1}, {-1, 1, 1},
    { 1,-1,-1}, { 1,-1, 1}, { 1, 1,-1}, { 1, 1, 1}
};

__device__ __forceinline__ float gelu_tanh(float x) {
    float x3  = x * x * x;
    float arg = 0.7978845608028654f * (x + 0.044715f * x3);
    float t;
    asm("tanh.approx.f32 %0, %1;" : "=f"(t) : "f"(arg));
    return 0.5f * x * (1.0f + t);
}

// order-preserving float <-> uint32
__device__ __forceinline__ unsigned int f2ord(float f) {
    unsigned int u = __float_as_uint(f);
    return (u & 0x80000000u) ? ~u : (u | 0x80000000u);
}
__device__ __forceinline__ float ord2f(unsigned int o) {
    unsigned int u = (o & 0x80000000u) ? (o & 0x7fffffffu) : ~o;
    return __uint_as_float(u);
}

// ---------------------------------------------------------------------------
// Fused binning: smem histogram -> smem scan -> scatter. One 512-thread block.
// ---------------------------------------------------------------------------
__global__ __launch_bounds__(NCELLS) void bin_kernel(const float* __restrict__ verts) {
    __shared__ int s_cnt[NCELLS];
    __shared__ int s_scan[NCELLS];
    const int t = threadIdx.x;
    s_cnt[t] = 0;
    __syncthreads();

    for (int i = t; i < N_PTS; i += NCELLS) {
        float rx = __fmul_rn(verts[i * 3 + 0], 32.0f);
        float ry = __fmul_rn(verts[i * 3 + 1], 32.0f);
        float rz = __fmul_rn(verts[i * 3 + 2], 32.0f);
        int cx = min(NC1 - 1, max(0, (int)(rx * 0.25f)));
        int cy = min(NC1 - 1, max(0, (int)(ry * 0.25f)));
        int cz = min(NC1 - 1, max(0, (int)(rz * 0.25f)));
        int c  = (cx * NC1 + cy) * NC1 + cz;
        g_cellid[i] = c;
        atomicAdd(&s_cnt[c], 1);
    }
    __syncthreads();

    int v = s_cnt[t];
    s_scan[t] = v;
    __syncthreads();
    for (int o = 1; o < NCELLS; o <<= 1) {
        int x = (t >= o) ? s_scan[t - o] : 0;
        __syncthreads();
        s_scan[t] += x;
        __syncthreads();
    }
    g_off[t + 1] = s_scan[t];
    if (t == 0) g_off[0] = 0;
    s_cnt[t] = s_scan[t] - v;   // exclusive offset = scatter cursor
    __syncthreads();

    for (int i = t; i < N_PTS; i += NCELLS) {
        float rx = __fmul_rn(verts[i * 3 + 0], 32.0f);
        float ry = __fmul_rn(verts[i * 3 + 1], 32.0f);
        float rz = __fmul_rn(verts[i * 3 + 2], 32.0f);
        float B  = __fadd_rn(__fadd_rn(__fmul_rn(rx, rx), __fmul_rn(ry, ry)),
                             __fmul_rn(rz, rz));
        int c   = g_cellid[i];
        int pos = atomicAdd(&s_cnt[c], 1);
        g_pts[pos]  = make_float4(rx, ry, rz, B);
        g_pidx[pos] = i;
    }
}

// ---------------------------------------------------------------------------
// Precompute P[n] = features[n] @ ew1[0:32]  (query-independent GEMM part).
// ---------------------------------------------------------------------------
__global__ __launch_bounds__(256) void pre_kernel(const float* __restrict__ feats,
                                                  const float* __restrict__ ew1) {
    const int n    = (blockIdx.x * 256 + threadIdx.x) >> 5;
    const int lane = threadIdx.x & 31;
    const int c0   = lane * 2;
    const float* f = feats + n * CIN;
    float a0 = 0.0f, a1 = 0.0f;
#pragma unroll
    for (int i = 0; i < CIN; i++) {
        float  fv = __ldg(f + i);
        float2 u  = __ldg((const float2*)(ew1 + i * CO + c0));
        a0 = fmaf(fv, u.x, a0);
        a1 = fmaf(fv, u.y, a1);
    }
    *(float2*)(g_P + n * CO + c0) = make_float2(a0, a1);
}

// ---------------------------------------------------------------------------
// KNN: near-to-far cell order with conservative per-cell culling.
// cellmin^2 is an exact geometric lower bound on true distance^2; the +0.01
// margin dominates the ~2e-3 worst-case rounding of the expanded-form d2,
// so no point of the true top-16 can be culled. Selection itself uses
// lexicographic (d2, idx) keys == top_k semantics (verified R10/R12).
// ---------------------------------------------------------------------------
__global__ __launch_bounds__(64) void knn_kernel(const float* __restrict__ gverts) {
    const int ix = blockIdx.x * 4 + threadIdx.x;
    const int iy = blockIdx.y * 4 + threadIdx.y;
    const int iz = blockIdx.z * 4 + threadIdx.z;
    const int m  = (ix * 32 + iy) * 32 + iz;

    const float qx = __fmul_rn(gverts[m * 3 + 0], 32.0f);
    const float qy = __fmul_rn(gverts[m * 3 + 1], 32.0f);
    const float qz = __fmul_rn(gverts[m * 3 + 2], 32.0f);
    const float A  = __fadd_rn(__fadd_rn(__fmul_rn(qx, qx), __fmul_rn(qy, qy)),
                               __fmul_rn(qz, qz));

    const int cx = min(NC1 - 1, max(0, (int)(qx * 0.25f)));
    const int cy = min(NC1 - 1, max(0, (int)(qy * 0.25f)));
    const int cz = min(NC1 - 1, max(0, (int)(qz * 0.25f)));

    const unsigned long long SENT =
        ((unsigned long long)f2ord(3.0e38f) << 32) | 0xffffffffull;
    unsigned long long kkey[KK];
#pragma unroll
    for (int t = 0; t < KK; t++) kkey[t] = SENT;
    unsigned long long worstkey = SENT;
    float worstf = 3.0e38f;
    int   wpos   = 0;

    // ---- r=1: 27 cells near-to-far with warp-cooperative culling ----
    for (int ci = 0; ci < 27; ci++) {
        const int xx = cx + c_off[ci][0];
        const int yy = cy + c_off[ci][1];
        const int zz = cz + c_off[ci][2];
        if (xx < 0 || xx >= NC1 || yy < 0 || yy >= NC1 ||
            zz < 0 || zz >= NC1) continue;

        // per-lane lower bound on dist^2 from q to this cell
        float lox = (float)(4 * xx), loy = (float)(4 * yy), loz = (float)(4 * zz);
        float dx = fmaxf(0.0f, fmaxf(lox - qx, qx - (lox + 4.0f)));
        float dy = fmaxf(0.0f, fmaxf(loy - qy, qy - (loy + 4.0f)));
        float dz = fmaxf(0.0f, fmaxf(loz - qz, qz - (loz + 4.0f)));
        float cm2 = fmaf(dx, dx, fmaf(dy, dy, dz * dz));
        bool need = (cm2 <= worstf + 0.01f);
        if (!__any_sync(0xffffffffu, need)) continue;

        const int c = (xx * NC1 + yy) * NC1 + zz;
        const int s = g_off[c], e = g_off[c + 1];
        for (int p = s; p < e; p++) {
            float4 pt = g_pts[p];
            float  D  = fmaf(qz, pt.z, fmaf(qy, pt.y, __fmul_rn(qx, pt.x)));
            float  d2 = __fsub_rn(__fadd_rn(A, pt.w), __fmul_rn(2.0f, D));
            if (d2 <= worstf) {
                unsigned long long key =
                    ((unsigned long long)f2ord(d2) << 32) |
                    (unsigned int)g_pidx[p];
                if (key < worstkey) {
#pragma unroll
                    for (int t = 0; t < KK; t++)
                        if (t == wpos) kkey[t] = key;
                    worstkey = kkey[0]; wpos = 0;
#pragma unroll
                    for (int t = 1; t < KK; t++)
                        if (kkey[t] > worstkey) { worstkey = kkey[t]; wpos = t; }
                    worstf = ord2f((unsigned int)(worstkey >> 32));
                }
            }
        }
    }

    // ---- rare fallback: rings r>=2 with prev-box exclusion (exact) ----
    int px0 = max(cx - 1, 0), px1 = min(cx + 1, NC1 - 1);
    int py0 = max(cy - 1, 0), py1 = min(cy + 1, NC1 - 1);
    int pz0 = max(cz - 1, 0), pz1 = min(cz + 1, NC1 - 1);

    for (int r = 1; r <= NC1; r++) {
        // coverage check for the CURRENT scanned box (r=1 box first)
        float cov = 1e30f;
        if (px0 > 0)       cov = fminf(cov, qx - (float)px0 * 4.0f);
        if (px1 < NC1 - 1) cov = fminf(cov, (float)(px1 + 1) * 4.0f - qx);
        if (py0 > 0)       cov = fminf(cov, qy - (float)py0 * 4.0f);
        if (py1 < NC1 - 1) cov = fminf(cov, (float)(py1 + 1) * 4.0f - qy);
        if (pz0 > 0)       cov = fminf(cov, qz - (float)pz0 * 4.0f);
        if (pz1 < NC1 - 1) cov = fminf(cov, (float)(pz1 + 1) * 4.0f - qz);
        if (worstf <= cov * cov * 0.999f - 1e-3f) break;

        const int rr = r + 1;
        const int nx0 = max(cx - rr, 0), nx1 = min(cx + rr, NC1 - 1);
        const int ny0 = max(cy - rr, 0), ny1 = min(cy + rr, NC1 - 1);
        const int nz0 = max(cz - rr, 0), nz1 = min(cz + rr, NC1 - 1);
        if (nx0 == px0 && nx1 == px1 && ny0 == py0 && ny1 == py1 &&
            nz0 == pz0 && nz1 == pz1) break;   // whole domain scanned

        for (int x = nx0; x <= nx1; x++)
        for (int y = ny0; y <= ny1; y++)
        for (int z = nz0; z <= nz1; z++) {
            if (x >= px0 && x <= px1 && y >= py0 && y <= py1 &&
                z >= pz0 && z <= pz1) continue;
            float lox = (float)(4 * x), loy = (float)(4 * y), loz = (float)(4 * z);
            float dx = fmaxf(0.0f, fmaxf(lox - qx, qx - (lox + 4.0f)));
            float dy = fmaxf(0.0f, fmaxf(loy - qy, qy - (loy + 4.0f)));
            float dz = fmaxf(0.0f, fmaxf(loz - qz, qz - (loz + 4.0f)));
            float cm2 = fmaf(dx, dx, fmaf(dy, dy, dz * dz));
            if (!__any_sync(0xffffffffu, cm2 <= worstf + 0.01f)) continue;

            const int c = (x * NC1 + y) * NC1 + z;
            const int s = g_off[c], e = g_off[c + 1];
            for (int p = s; p < e; p++) {
                float4 pt = g_pts[p];
                float  D  = fmaf(qz, pt.z, fmaf(qy, pt.y, __fmul_rn(qx, pt.x)));
                float  d2 = __fsub_rn(__fadd_rn(A, pt.w), __fmul_rn(2.0f, D));
                if (d2 <= worstf) {
                    unsigned long long key =
                        ((unsigned long long)f2ord(d2) << 32) |
                        (unsigned int)g_pidx[p];
                    if (key < worstkey) {
#pragma unroll
                        for (int t = 0; t < KK; t++)
                            if (t == wpos) kkey[t] = key;
                        worstkey = kkey[0]; wpos = 0;
#pragma unroll
                        for (int t = 1; t < KK; t++)
                            if (kkey[t] > worstkey) { worstkey = kkey[t]; wpos = t; }
                        worstf = ord2f((unsigned int)(worstkey >> 32));
                    }
                }
            }
        }
        px0 = nx0; px1 = nx1; py0 = ny0; py1 = ny1; pz0 = nz0; pz1 = nz1;
    }

    // canonical order = ascending (d2, idx) = top_k order
#pragma unroll
    for (int rd = 0; rd < KK; rd++) {
#pragma unroll
        for (int t = (rd & 1); t + 1 < KK; t += 2) {
            if (kkey[t] > kkey[t + 1]) {
                unsigned long long tmp = kkey[t]; kkey[t] = kkey[t + 1]; kkey[t + 1] = tmp;
            }
        }
    }
#pragma unroll
    for (int t = 0; t < KK; t++)
        g_knn[m * KK + t] = (int)(kkey[t] & 0xffffffffu);
}

// ---------------------------------------------------------------------------
// Edge kernel (UNCHANGED, verified @41us): P[idx] + eb1 + rel_pos@ew1[32:35];
// LN; GELU; K-mean -> g_gmean.
// ---------------------------------------------------------------------------
__global__ __launch_bounds__(256) void edge_kernel(
    const float* __restrict__ verts, const float* __restrict__ gverts,
    const float* __restrict__ ew1, const float* __restrict__ eb1,
    const float* __restrict__ eg1, const float* __restrict__ ebt1)
{
    __shared__ int   s_idx[8][KK];
    __shared__ float s_rp[8][KK][4];

    const int tid  = threadIdx.x;
    const int w    = tid >> 5;
    const int lane = tid & 31;
    const int m    = blockIdx.x * 8 + w;
    const int c0   = lane * 2;

    const float2 w32 = __ldg((const float2*)(ew1 + 32 * CO + c0));
    const float2 w33 = __ldg((const float2*)(ew1 + 33 * CO + c0));
    const float2 w34 = __ldg((const float2*)(ew1 + 34 * CO + c0));
    const float2 p_eb1  = *(const float2*)(eb1  + c0);
    const float2 p_eg1  = *(const float2*)(eg1  + c0);
    const float2 p_ebt1 = *(const float2*)(ebt1 + c0);

    if (lane < KK) {
        int idx = g_knn[m * KK + lane];
        s_idx[w][lane] = idx;
        s_rp[w][lane][0] = verts[idx * 3 + 0] - gverts[m * 3 + 0];
        s_rp[w][lane][1] = verts[idx * 3 + 1] - gverts[m * 3 + 1];
        s_rp[w][lane][2] = verts[idx * 3 + 2] - gverts[m * 3 + 2];
    }
    __syncwarp();

    float gb0 = 0.0f, gb1 = 0.0f;
#pragma unroll
    for (int pass = 0; pass < 2; pass++) {
        const int r0 = pass * 8;
        float acc0[8], acc1[8];
#pragma unroll
        for (int r = 0; r < 8; r++) {
            int    idx = s_idx[w][r0 + r];
            float2 p   = __ldg((const float2*)(g_P + idx * CO + c0));
            float  rx  = s_rp[w][r0 + r][0];
            float  ry  = s_rp[w][r0 + r][1];
            float  rz  = s_rp[w][r0 + r][2];
            float a0 = p.x + p_eb1.x;
            float a1 = p.y + p_eb1.y;
            a0 = fmaf(rx, w32.x, a0); a1 = fmaf(rx, w32.y, a1);
            a0 = fmaf(ry, w33.x, a0); a1 = fmaf(ry, w33.y, a1);
            a0 = fmaf(rz, w34.x, a0); a1 = fmaf(rz, w34.y, a1);
            acc0[r] = a0; acc1[r] = a1;
        }
#pragma unroll
        for (int r = 0; r < 8; r++) {
            float a0 = acc0[r], a1 = acc1[r];
            float s  = a0 + a1;
            float ss = fmaf(a0, a0, a1 * a1);
#pragma unroll
            for (int o = 16; o > 0; o >>= 1) {
                s  += __shfl_xor_sync(0xffffffffu, s,  o);
                ss += __shfl_xor_sync(0xffffffffu, ss, o);
            }
            float mean = s * (1.0f / 64.0f);
            float var  = ss * (1.0f / 64.0f) - mean * mean;
            float rstd = rsqrtf(var + 1e-5f);
            float h0 = fmaf((a0 - mean) * rstd, p_eg1.x, p_ebt1.x);
            float h1 = fmaf((a1 - mean) * rstd, p_eg1.y, p_ebt1.y);
            gb0 += gelu_tanh(h0);
            gb1 += gelu_tanh(h1);
        }
    }
    gb0 *= (1.0f / 16.0f);
    gb1 *= (1.0f / 16.0f);
    *(float2*)(g_gmean + m * CO + c0) = make_float2(gb0, gb1);
}

// ---------------------------------------------------------------------------
// Out kernel (UNCHANGED, verified): warp handles 4 vertices.
// ---------------------------------------------------------------------------
__global__ __launch_bounds__(256) void out_kernel(
    const float* __restrict__ gfeat,
    const float* __restrict__ ew2, const float* __restrict__ eb2,
    const float* __restrict__ ow1, const float* __restrict__ ob1,
    const float* __restrict__ og1, const float* __restrict__ obt1,
    const float* __restrict__ ow2, const float* __restrict__ ob2,
    float* __restrict__ out)
{
    __shared__ __align__(16) float4 s_x[8][160];

    const int tid  = threadIdx.x;
    const int w    = tid >> 5;
    const int lane = tid & 31;
    const int c0   = lane * 2;
    const int v0   = blockIdx.x * 32 + w * 4;

    for (int i = lane; i < CO; i += 32)
        s_x[w][i] = make_float4(g_gmean[(v0 + 0) * CO + i], g_gmean[(v0 + 1) * CO + i],
                                g_gmean[(v0 + 2) * CO + i], g_gmean[(v0 + 3) * CO + i]);
    for (int i = lane; i < 96; i += 32)
        s_x[w][CO + i] = make_float4(gfeat[(v0 + 0) * 96 + i], gfeat[(v0 + 1) * 96 + i],
                                     gfeat[(v0 + 2) * 96 + i], gfeat[(v0 + 3) * 96 + i]);
    __syncwarp();

    const float2 p_eb2 = *(const float2*)(eb2 + c0);
    float a00 = p_eb2.x, a01 = p_eb2.y, a10 = p_eb2.x, a11 = p_eb2.y;
    float a20 = p_eb2.x, a21 = p_eb2.y, a30 = p_eb2.x, a31 = p_eb2.y;
#pragma unroll 8
    for (int i = 0; i < CO; i++) {
        float4 x = s_x[w][i];
        float2 u = __ldg((const float2*)(ew2 + i * CO + c0));
        a00 = fmaf(x.x, u.x, a00); a01 = fmaf(x.x, u.y, a01);
        a10 = fmaf(x.y, u.x, a10); a11 = fmaf(x.y, u.y, a11);
        a20 = fmaf(x.z, u.x, a20); a21 = fmaf(x.z, u.y, a21);
        a30 = fmaf(x.w, u.x, a30); a31 = fmaf(x.w, u.y, a31);
    }
    __syncwarp();
    s_x[w][c0]     = make_float4(a00, a10, a20, a30);
    s_x[w][c0 + 1] = make_float4(a01, a11, a21, a31);
    __syncwarp();

    const float2 p_ob1 = *(const float2*)(ob1 + c0);
    float o00 = p_ob1.x, o01 = p_ob1.y, o10 = p_ob1.x, o11 = p_ob1.y;
    float o20 = p_ob1.x, o21 = p_ob1.y, o30 = p_ob1.x, o31 = p_ob1.y;
#pragma unroll 8
    for (int i = 0; i < CO + 96; i++) {
        float4 x = s_x[w][i];
        float2 u = __ldg((const float2*)(ow1 + i * CO + c0));
        o00 = fmaf(x.x, u.x, o00); o01 = fmaf(x.x, u.y, o01);
        o10 = fmaf(x.y, u.x, o10); o11 = fmaf(x.y, u.y, o11);
        o20 = fmaf(x.z, u.x, o20); o21 = fmaf(x.z, u.y, o21);
        o30 = fmaf(x.w, u.x, o30); o31 = fmaf(x.w, u.y, o31);
    }

    const float2 p_og1  = *(const float2*)(og1  + c0);
    const float2 p_obt1 = *(const float2*)(obt1 + c0);
    float g0[4], g1[4];
    float ov0[4] = {o00, o10, o20, o30};
    float ov1[4] = {o01, o11, o21, o31};
#pragma unroll
    for (int v = 0; v < 4; v++) {
        float b0 = ov0[v], b1 = ov1[v];
        float s  = b0 + b1;
        float ss = fmaf(b0, b0, b1 * b1);
#pragma unroll
        for (int o = 16; o > 0; o >>= 1) {
            s  += __shfl_xor_sync(0xffffffffu, s,  o);
            ss += __shfl_xor_sync(0xffffffffu, ss, o);
        }
        float mean = s * (1.0f / 64.0f);
        float var  = ss * (1.0f / 64.0f) - mean * mean;
        float rstd = rsqrtf(var + 1e-5f);
        g0[v] = gelu_tanh(fmaf((b0 - mean) * rstd, p_og1.x, p_obt1.x));
        g1[v] = gelu_tanh(fmaf((b1 - mean) * rstd, p_og1.y, p_obt1.y));
    }
    __syncwarp();
    s_x[w][c0]     = make_float4(g0[0], g0[1], g0[2], g0[3]);
    s_x[w][c0 + 1] = make_float4(g1[0], g1[1], g1[2], g1[3]);
    __syncwarp();

    const float2 p_ob2 = *(const float2*)(ob2 + c0);
    float f00 = p_ob2.x, f01 = p_ob2.y, f10 = p_ob2.x, f11 = p_ob2.y;
    float f20 = p_ob2.x, f21 = p_ob2.y, f30 = p_ob2.x, f31 = p_ob2.y;
#pragma unroll 8
    for (int j = 0; j < CO; j++) {
        float4 x = s_x[w][j];
        float2 u = __ldg((const float2*)(ow2 + j * CO + c0));
        f00 = fmaf(x.x, u.x, f00); f01 = fmaf(x.x, u.y, f01);
        f10 = fmaf(x.y, u.x, f10); f11 = fmaf(x.y, u.y, f11);
        f20 = fmaf(x.z, u.x, f20); f21 = fmaf(x.z, u.y, f21);
        f30 = fmaf(x.w, u.x, f30); f31 = fmaf(x.w, u.y, f31);
    }
    *(float2*)(out + (v0 + 0) * CO + c0) = make_float2(f00, f01);
    *(float2*)(out + (v0 + 1) * CO + c0) = make_float2(f10, f11);
    *(float2*)(out + (v0 + 2) * CO + c0) = make_float2(f20, f21);
    *(float2*)(out + (v0 + 3) * CO + c0) = make_float2(f30, f31);
}

// ---------------------------------------------------------------------------
extern "C" void kernel_launch(void* const* d_in, const int* in_sizes, int n_in,
                              void* d_out, int out_size) {
    const float* vertices = (const float*)d_in[0];
    const float* features = (const float*)d_in[1];
    const float* gverts   = (const float*)d_in[2];
    const float* gfeat    = (const float*)d_in[3];
    const float* ew1  = (const float*)d_in[4];
    const float* eb1  = (const float*)d_in[5];
    const float* eg1  = (const float*)d_in[6];
    const float* ebt1 = (const float*)d_in[7];
    const float* ew2  = (const float*)d_in[8];
    const float* eb2  = (const float*)d_in[9];
    const float* ow1  = (const float*)d_in[10];
    const float* ob1  = (const float*)d_in[11];
    const float* og1  = (const float*)d_in[12];
    const float* obt1 = (const float*)d_in[13];
    const float* ow2  = (const float*)d_in[14];
    const float* ob2  = (const float*)d_in[15];
    float* out = (float*)d_out;

    bin_kernel<<<1, NCELLS>>>(vertices);
    knn_kernel<<<dim3(8, 8, 8), dim3(4, 4, 4)>>>(gverts);
    pre_kernel<<<N_PTS * 32 / 256, 256>>>(features, ew1);
    edge_kernel<<<M_TOT / 8, 256>>>(vertices, gverts, ew1, eb1, eg1, ebt1);
    out_kernel<<<M_TOT / 32, 256>>>(gfeat, ew2, eb2, ow1, ob1,
                                    og1, obt1, ow2, ob2, out);
}

// round 15
// speedup vs baseline: 6.5886x; 1.0447x over previous
#include <cuda_runtime.h>
#include <math.h>

#define M_TOT 32768
#define N_PTS 8192
#define KK    16
#define CIN   32
#define CO    64
#define NC1   8
#define NCELLS 512

// scratch (all __device__, no allocs)
__device__ int    g_cellid[N_PTS];
__device__ int    g_off[NCELLS + 1];
__device__ float4 g_pts[N_PTS];
__device__ int    g_pidx[N_PTS];
__device__ int    g_knn[M_TOT * KK];
__device__ float  g_gmean[M_TOT * CO];   // 8 MB: post-gelu K-mean
__device__ float  g_P[N_PTS * CO];       // 2 MB: feats@ew1[0:32] + eb1
__device__ float4 g_aux[N_PTS];          // (sP, sP2, d32, d33)
__device__ float  g_aux2[N_PTS];         // d34
__device__ float  g_wscal[9];            // sw32,sw33,sw34,s3232,s3333,s3434,s3233,s3234,s3334

// 27 neighbor offsets ordered near-to-far
__constant__ signed char c_off[27][3] = {
    { 0, 0, 0},
    {-1, 0, 0}, { 1, 0, 0}, { 0,-1, 0}, { 0, 1, 0}, { 0, 0,-1}, { 0, 0, 1},
    {-1,-1, 0}, {-1, 1, 0}, { 1,-1, 0}, { 1, 1, 0},
    {-1, 0,-1}, {-1, 0, 1}, { 1, 0,-1}, { 1, 0, 1},
    { 0,-1,-1}, { 0,-1, 1}, { 0, 1,-1}, { 0, 1, 1},
    {-1,-1,-1}, {-1,-1, 1}, {-1, 1,-1}, {-1, 1, 1},
    { 1,-1,-1}, { 1,-1, 1}, { 1, 1,-1}, { 1, 1, 1}
};

__device__ __forceinline__ float gelu_tanh(float x) {
    float x3  = x * x * x;
    float arg = 0.7978845608028654f * (x + 0.044715f * x3);
    float t;
    asm("tanh.approx.f32 %0, %1;" : "=f"(t) : "f"(arg));
    return 0.5f * x * (1.0f + t);
}

__device__ __forceinline__ float bfly_sum(float v) {
#pragma unroll
    for (int o = 16; o > 0; o >>= 1)
        v += __shfl_xor_sync(0xffffffffu, v, o);
    return v;
}

// order-preserving float <-> uint32
__device__ __forceinline__ unsigned int f2ord(float f) {
    unsigned int u = __float_as_uint(f);
    return (u & 0x80000000u) ? ~u : (u | 0x80000000u);
}
__device__ __forceinline__ float ord2f(unsigned int o) {
    unsigned int u = (o & 0x80000000u) ? (o & 0x7fffffffu) : ~o;
    return __uint_as_float(u);
}

// ---------------------------------------------------------------------------
// Fused binning (UNCHANGED, verified)
// ---------------------------------------------------------------------------
__global__ __launch_bounds__(NCELLS) void bin_kernel(const float* __restrict__ verts) {
    __shared__ int s_cnt[NCELLS];
    __shared__ int s_scan[NCELLS];
    const int t = threadIdx.x;
    s_cnt[t] = 0;
    __syncthreads();

    for (int i = t; i < N_PTS; i += NCELLS) {
        float rx = __fmul_rn(verts[i * 3 + 0], 32.0f);
        float ry = __fmul_rn(verts[i * 3 + 1], 32.0f);
        float rz = __fmul_rn(verts[i * 3 + 2], 32.0f);
        int cx = min(NC1 - 1, max(0, (int)(rx * 0.25f)));
        int cy = min(NC1 - 1, max(0, (int)(ry * 0.25f)));
        int cz = min(NC1 - 1, max(0, (int)(rz * 0.25f)));
        int c  = (cx * NC1 + cy) * NC1 + cz;
        g_cellid[i] = c;
        atomicAdd(&s_cnt[c], 1);
    }
    __syncthreads();

    int v = s_cnt[t];
    s_scan[t] = v;
    __syncthreads();
    for (int o = 1; o < NCELLS; o <<= 1) {
        int x = (t >= o) ? s_scan[t - o] : 0;
        __syncthreads();
        s_scan[t] += x;
        __syncthreads();
    }
    g_off[t + 1] = s_scan[t];
    if (t == 0) g_off[0] = 0;
    s_cnt[t] = s_scan[t] - v;
    __syncthreads();

    for (int i = t; i < N_PTS; i += NCELLS) {
        float rx = __fmul_rn(verts[i * 3 + 0], 32.0f);
        float ry = __fmul_rn(verts[i * 3 + 1], 32.0f);
        float rz = __fmul_rn(verts[i * 3 + 2], 32.0f);
        float B  = __fadd_rn(__fadd_rn(__fmul_rn(rx, rx), __fmul_rn(ry, ry)),
                             __fmul_rn(rz, rz));
        int c   = g_cellid[i];
        int pos = atomicAdd(&s_cnt[c], 1);
        g_pts[pos]  = make_float4(rx, ry, rz, B);
        g_pidx[pos] = i;
    }
}

// ---------------------------------------------------------------------------
// Weight scalars: 9 reductions over the 64-channel rel-pos weight rows.
// ---------------------------------------------------------------------------
__global__ void wscal_kernel(const float* __restrict__ ew1) {
    const int lane = threadIdx.x;
    const int c0   = lane * 2;
    float2 w32 = __ldg((const float2*)(ew1 + 32 * CO + c0));
    float2 w33 = __ldg((const float2*)(ew1 + 33 * CO + c0));
    float2 w34 = __ldg((const float2*)(ew1 + 34 * CO + c0));
    float r0 = bfly_sum(w32.x + w32.y);
    float r1 = bfly_sum(w33.x + w33.y);
    float r2 = bfly_sum(w34.x + w34.y);
    float r3 = bfly_sum(fmaf(w32.x, w32.x, w32.y * w32.y));
    float r4 = bfly_sum(fmaf(w33.x, w33.x, w33.y * w33.y));
    float r5 = bfly_sum(fmaf(w34.x, w34.x, w34.y * w34.y));
    float r6 = bfly_sum(fmaf(w32.x, w33.x, w32.y * w33.y));
    float r7 = bfly_sum(fmaf(w32.x, w34.x, w32.y * w34.y));
    float r8 = bfly_sum(fmaf(w33.x, w34.x, w33.y * w34.y));
    if (lane == 0) {
        g_wscal[0] = r0; g_wscal[1] = r1; g_wscal[2] = r2;
        g_wscal[3] = r3; g_wscal[4] = r4; g_wscal[5] = r5;
        g_wscal[6] = r6; g_wscal[7] = r7; g_wscal[8] = r8;
    }
}

// ---------------------------------------------------------------------------
// Precompute P'[n] = feats[n]@ew1[0:32] + eb1, plus per-point aggregates
// sP, sP2, d32, d33, d34 for analytic LayerNorm statistics.
// ---------------------------------------------------------------------------
__global__ __launch_bounds__(256) void pre_kernel(const float* __restrict__ feats,
                                                  const float* __restrict__ ew1,
                                                  const float* __restrict__ eb1) {
    const int n    = (blockIdx.x * 256 + threadIdx.x) >> 5;
    const int lane = threadIdx.x & 31;
    const int c0   = lane * 2;
    const float* f = feats + n * CIN;
    float2 b = __ldg((const float2*)(eb1 + c0));
    float a0 = b.x, a1 = b.y;
#pragma unroll
    for (int i = 0; i < CIN; i++) {
        float  fv = __ldg(f + i);
        float2 u  = __ldg((const float2*)(ew1 + i * CO + c0));
        a0 = fmaf(fv, u.x, a0);
        a1 = fmaf(fv, u.y, a1);
    }
    *(float2*)(g_P + n * CO + c0) = make_float2(a0, a1);

    float2 w32 = __ldg((const float2*)(ew1 + 32 * CO + c0));
    float2 w33 = __ldg((const float2*)(ew1 + 33 * CO + c0));
    float2 w34 = __ldg((const float2*)(ew1 + 34 * CO + c0));
    float sp  = bfly_sum(a0 + a1);
    float sp2 = bfly_sum(fmaf(a0, a0, a1 * a1));
    float d32 = bfly_sum(fmaf(a0, w32.x, a1 * w32.y));
    float d33 = bfly_sum(fmaf(a0, w33.x, a1 * w33.y));
    float d34 = bfly_sum(fmaf(a0, w34.x, a1 * w34.y));
    if (lane == 0) {
        g_aux[n]  = make_float4(sp, sp2, d32, d33);
        g_aux2[n] = d34;
    }
}

// ---------------------------------------------------------------------------
// KNN (UNCHANGED, verified @R13)
// ---------------------------------------------------------------------------
__global__ __launch_bounds__(64) void knn_kernel(const float* __restrict__ gverts) {
    const int ix = blockIdx.x * 4 + threadIdx.x;
    const int iy = blockIdx.y * 4 + threadIdx.y;
    const int iz = blockIdx.z * 4 + threadIdx.z;
    const int m  = (ix * 32 + iy) * 32 + iz;

    const float qx = __fmul_rn(gverts[m * 3 + 0], 32.0f);
    const float qy = __fmul_rn(gverts[m * 3 + 1], 32.0f);
    const float qz = __fmul_rn(gverts[m * 3 + 2], 32.0f);
    const float A  = __fadd_rn(__fadd_rn(__fmul_rn(qx, qx), __fmul_rn(qy, qy)),
                               __fmul_rn(qz, qz));

    const int cx = min(NC1 - 1, max(0, (int)(qx * 0.25f)));
    const int cy = min(NC1 - 1, max(0, (int)(qy * 0.25f)));
    const int cz = min(NC1 - 1, max(0, (int)(qz * 0.25f)));

    const unsigned long long SENT =
        ((unsigned long long)f2ord(3.0e38f) << 32) | 0xffffffffull;
    unsigned long long kkey[KK];
#pragma unroll
    for (int t = 0; t < KK; t++) kkey[t] = SENT;
    unsigned long long worstkey = SENT;
    float worstf = 3.0e38f;
    int   wpos   = 0;

    for (int ci = 0; ci < 27; ci++) {
        const int xx = cx + c_off[ci][0];
        const int yy = cy + c_off[ci][1];
        const int zz = cz + c_off[ci][2];
        if (xx < 0 || xx >= NC1 || yy < 0 || yy >= NC1 ||
            zz < 0 || zz >= NC1) continue;

        float lox = (float)(4 * xx), loy = (float)(4 * yy), loz = (float)(4 * zz);
        float dx = fmaxf(0.0f, fmaxf(lox - qx, qx - (lox + 4.0f)));
        float dy = fmaxf(0.0f, fmaxf(loy - qy, qy - (loy + 4.0f)));
        float dz = fmaxf(0.0f, fmaxf(loz - qz, qz - (loz + 4.0f)));
        float cm2 = fmaf(dx, dx, fmaf(dy, dy, dz * dz));
        bool need = (cm2 <= worstf + 0.01f);
        if (!__any_sync(0xffffffffu, need)) continue;

        const int c = (xx * NC1 + yy) * NC1 + zz;
        const int s = g_off[c], e = g_off[c + 1];
        for (int p = s; p < e; p++) {
            float4 pt = g_pts[p];
            float  D  = fmaf(qz, pt.z, fmaf(qy, pt.y, __fmul_rn(qx, pt.x)));
            float  d2 = __fsub_rn(__fadd_rn(A, pt.w), __fmul_rn(2.0f, D));
            if (d2 <= worstf) {
                unsigned long long key =
                    ((unsigned long long)f2ord(d2) << 32) |
                    (unsigned int)g_pidx[p];
                if (key < worstkey) {
#pragma unroll
                    for (int t = 0; t < KK; t++)
                        if (t == wpos) kkey[t] = key;
                    worstkey = kkey[0]; wpos = 0;
#pragma unroll
                    for (int t = 1; t < KK; t++)
                        if (kkey[t] > worstkey) { worstkey = kkey[t]; wpos = t; }
                    worstf = ord2f((unsigned int)(worstkey >> 32));
                }
            }
        }
    }

    int px0 = max(cx - 1, 0), px1 = min(cx + 1, NC1 - 1);
    int py0 = max(cy - 1, 0), py1 = min(cy + 1, NC1 - 1);
    int pz0 = max(cz - 1, 0), pz1 = min(cz + 1, NC1 - 1);

    for (int r = 1; r <= NC1; r++) {
        float cov = 1e30f;
        if (px0 > 0)       cov = fminf(cov, qx - (float)px0 * 4.0f);
        if (px1 < NC1 - 1) cov = fminf(cov, (float)(px1 + 1) * 4.0f - qx);
        if (py0 > 0)       cov = fminf(cov, qy - (float)py0 * 4.0f);
        if (py1 < NC1 - 1) cov = fminf(cov, (float)(py1 + 1) * 4.0f - qy);
        if (pz0 > 0)       cov = fminf(cov, qz - (float)pz0 * 4.0f);
        if (pz1 < NC1 - 1) cov = fminf(cov, (float)(pz1 + 1) * 4.0f - qz);
        if (worstf <= cov * cov * 0.999f - 1e-3f) break;

        const int rr = r + 1;
        const int nx0 = max(cx - rr, 0), nx1 = min(cx + rr, NC1 - 1);
        const int ny0 = max(cy - rr, 0), ny1 = min(cy + rr, NC1 - 1);
        const int nz0 = max(cz - rr, 0), nz1 = min(cz + rr, NC1 - 1);
        if (nx0 == px0 && nx1 == px1 && ny0 == py0 && ny1 == py1 &&
            nz0 == pz0 && nz1 == pz1) break;

        for (int x = nx0; x <= nx1; x++)
        for (int y = ny0; y <= ny1; y++)
        for (int z = nz0; z <= nz1; z++) {
            if (x >= px0 && x <= px1 && y >= py0 && y <= py1 &&
                z >= pz0 && z <= pz1) continue;
            float lox = (float)(4 * x), loy = (float)(4 * y), loz = (float)(4 * z);
            float dx = fmaxf(0.0f, fmaxf(lox - qx, qx - (lox + 4.0f)));
            float dy = fmaxf(0.0f, fmaxf(loy - qy, qy - (loy + 4.0f)));
            float dz = fmaxf(0.0f, fmaxf(loz - qz, qz - (loz + 4.0f)));
            float cm2 = fmaf(dx, dx, fmaf(dy, dy, dz * dz));
            if (!__any_sync(0xffffffffu, cm2 <= worstf + 0.01f)) continue;

            const int c = (x * NC1 + y) * NC1 + z;
            const int s = g_off[c], e = g_off[c + 1];
            for (int p = s; p < e; p++) {
                float4 pt = g_pts[p];
                float  D  = fmaf(qz, pt.z, fmaf(qy, pt.y, __fmul_rn(qx, pt.x)));
                float  d2 = __fsub_rn(__fadd_rn(A, pt.w), __fmul_rn(2.0f, D));
                if (d2 <= worstf) {
                    unsigned long long key =
                        ((unsigned long long)f2ord(d2) << 32) |
                        (unsigned int)g_pidx[p];
                    if (key < worstkey) {
#pragma unroll
                        for (int t = 0; t < KK; t++)
                            if (t == wpos) kkey[t] = key;
                        worstkey = kkey[0]; wpos = 0;
#pragma unroll
                        for (int t = 1; t < KK; t++)
                            if (kkey[t] > worstkey) { worstkey = kkey[t]; wpos = t; }
                        worstf = ord2f((unsigned int)(worstkey >> 32));
                    }
                }
            }
        }
        px0 = nx0; px1 = nx1; py0 = ny0; py1 = ny1; pz0 = nz0; pz1 = nz1;
    }

#pragma unroll
    for (int rd = 0; rd < KK; rd++) {
#pragma unroll
        for (int t = (rd & 1); t + 1 < KK; t += 2) {
            if (kkey[t] > kkey[t + 1]) {
                unsigned long long tmp = kkey[t]; kkey[t] = kkey[t + 1]; kkey[t + 1] = tmp;
            }
        }
    }
#pragma unroll
    for (int t = 0; t < KK; t++)
        g_knn[m * KK + t] = (int)(kkey[t] & 0xffffffffu);
}

// ---------------------------------------------------------------------------
// Edge kernel with ANALYTIC LayerNorm stats: lane r computes row r's
// mean/rstd from per-point aggregates (no warp reductions); 2 shfl broadcasts
// per row replace the former 20-op butterfly pair.
// ---------------------------------------------------------------------------
__global__ __launch_bounds__(256) void edge_kernel(
    const float* __restrict__ verts, const float* __restrict__ gverts,
    const float* __restrict__ ew1,
    const float* __restrict__ eg1, const float* __restrict__ ebt1)
{
    __shared__ int   s_idx[8][KK];
    __shared__ float s_rp[8][KK][4];

    const int tid  = threadIdx.x;
    const int w    = tid >> 5;
    const int lane = tid & 31;
    const int m    = blockIdx.x * 8 + w;
    const int c0   = lane * 2;

    const float2 w32 = __ldg((const float2*)(ew1 + 32 * CO + c0));
    const float2 w33 = __ldg((const float2*)(ew1 + 33 * CO + c0));
    const float2 w34 = __ldg((const float2*)(ew1 + 34 * CO + c0));
    const float2 p_eg1  = *(const float2*)(eg1  + c0);
    const float2 p_ebt1 = *(const float2*)(ebt1 + c0);

    const float sw32 = __ldg(&g_wscal[0]), sw33 = __ldg(&g_wscal[1]);
    const float sw34 = __ldg(&g_wscal[2]);
    const float s3232 = __ldg(&g_wscal[3]), s3333 = __ldg(&g_wscal[4]);
    const float s3434 = __ldg(&g_wscal[5]);
    const float s3233 = __ldg(&g_wscal[6]), s3234 = __ldg(&g_wscal[7]);
    const float s3334 = __ldg(&g_wscal[8]);

    if (lane < KK) {
        int idx = g_knn[m * KK + lane];
        s_idx[w][lane] = idx;
        s_rp[w][lane][0] = verts[idx * 3 + 0] - gverts[m * 3 + 0];
        s_rp[w][lane][1] = verts[idx * 3 + 1] - gverts[m * 3 + 1];
        s_rp[w][lane][2] = verts[idx * 3 + 2] - gverts[m * 3 + 2];
    }
    __syncwarp();

    // lane r (r < 16): analytic LN stats for row r
    float my_mean = 0.0f, my_rstd = 1.0f;
    if (lane < KK) {
        int    idxr = s_idx[w][lane];
        float  rx = s_rp[w][lane][0];
        float  ry = s_rp[w][lane][1];
        float  rz = s_rp[w][lane][2];
        float4 au   = __ldg(&g_aux[idxr]);
        float  d34v = __ldg(&g_aux2[idxr]);
        float sum = au.x + rx * sw32 + ry * sw33 + rz * sw34;
        float ss  = au.y
                  + 2.0f * (rx * au.z + ry * au.w + rz * d34v)
                  + rx * rx * s3232 + ry * ry * s3333 + rz * rz * s3434
                  + 2.0f * (rx * ry * s3233 + rx * rz * s3234 + ry * rz * s3334);
        my_mean = sum * (1.0f / 64.0f);
        float var = ss * (1.0f / 64.0f) - my_mean * my_mean;
        my_rstd = rsqrtf(var + 1e-5f);
    }
    __syncwarp();

    float gb0 = 0.0f, gb1 = 0.0f;
#pragma unroll
    for (int r = 0; r < KK; r++) {
        float mean = __shfl_sync(0xffffffffu, my_mean, r);
        float rstd = __shfl_sync(0xffffffffu, my_rstd, r);
        int    idx = s_idx[w][r];
        float  rx  = s_rp[w][r][0];
        float  ry  = s_rp[w][r][1];
        float  rz  = s_rp[w][r][2];
        float2 p   = __ldg((const float2*)(g_P + idx * CO + c0));
        float a0 = p.x, a1 = p.y;
        a0 = fmaf(rx, w32.x, a0); a1 = fmaf(rx, w32.y, a1);
        a0 = fmaf(ry, w33.x, a0); a1 = fmaf(ry, w33.y, a1);
        a0 = fmaf(rz, w34.x, a0); a1 = fmaf(rz, w34.y, a1);
        float h0 = fmaf((a0 - mean) * rstd, p_eg1.x, p_ebt1.x);
        float h1 = fmaf((a1 - mean) * rstd, p_eg1.y, p_ebt1.y);
        gb0 += gelu_tanh(h0);
        gb1 += gelu_tanh(h1);
    }
    gb0 *= (1.0f / 16.0f);
    gb1 *= (1.0f / 16.0f);
    *(float2*)(g_gmean + m * CO + c0) = make_float2(gb0, gb1);
}

// ---------------------------------------------------------------------------
// Out kernel (R12-verified, butterfly reductions restored)
// ---------------------------------------------------------------------------
__global__ __launch_bounds__(256) void out_kernel(
    const float* __restrict__ gfeat,
    const float* __restrict__ ew2, const float* __restrict__ eb2,
    const float* __restrict__ ow1, const float* __restrict__ ob1,
    const float* __restrict__ og1, const float* __restrict__ obt1,
    const float* __restrict__ ow2, const float* __restrict__ ob2,
    float* __restrict__ out)
{
    __shared__ __align__(16) float4 s_x[8][160];

    const int tid  = threadIdx.x;
    const int w    = tid >> 5;
    const int lane = tid & 31;
    const int c0   = lane * 2;
    const int v0   = blockIdx.x * 32 + w * 4;

    for (int i = lane; i < CO; i += 32)
        s_x[w][i] = make_float4(g_gmean[(v0 + 0) * CO + i], g_gmean[(v0 + 1) * CO + i],
                                g_gmean[(v0 + 2) * CO + i], g_gmean[(v0 + 3) * CO + i]);
    for (int i = lane; i < 96; i += 32)
        s_x[w][CO + i] = make_float4(gfeat[(v0 + 0) * 96 + i], gfeat[(v0 + 1) * 96 + i],
                                     gfeat[(v0 + 2) * 96 + i], gfeat[(v0 + 3) * 96 + i]);
    __syncwarp();

    const float2 p_eb2 = *(const float2*)(eb2 + c0);
    float a00 = p_eb2.x, a01 = p_eb2.y, a10 = p_eb2.x, a11 = p_eb2.y;
    float a20 = p_eb2.x, a21 = p_eb2.y, a30 = p_eb2.x, a31 = p_eb2.y;
#pragma unroll 8
    for (int i = 0; i < CO; i++) {
        float4 x = s_x[w][i];
        float2 u = __ldg((const float2*)(ew2 + i * CO + c0));
        a00 = fmaf(x.x, u.x, a00); a01 = fmaf(x.x, u.y, a01);
        a10 = fmaf(x.y, u.x, a10); a11 = fmaf(x.y, u.y, a11);
        a20 = fmaf(x.z, u.x, a20); a21 = fmaf(x.z, u.y, a21);
        a30 = fmaf(x.w, u.x, a30); a31 = fmaf(x.w, u.y, a31);
    }
    __syncwarp();
    s_x[w][c0]     = make_float4(a00, a10, a20, a30);
    s_x[w][c0 + 1] = make_float4(a01, a11, a21, a31);
    __syncwarp();

    const float2 p_ob1 = *(const float2*)(ob1 + c0);
    float o00 = p_ob1.x, o01 = p_ob1.y, o10 = p_ob1.x, o11 = p_ob1.y;
    float o20 = p_ob1.x, o21 = p_ob1.y, o30 = p_ob1.x, o31 = p_ob1.y;
#pragma unroll 8
    for (int i = 0; i < CO + 96; i++) {
        float4 x = s_x[w][i];
        float2 u = __ldg((const float2*)(ow1 + i * CO + c0));
        o00 = fmaf(x.x, u.x, o00); o01 = fmaf(x.x, u.y, o01);
        o10 = fmaf(x.y, u.x, o10); o11 = fmaf(x.y, u.y, o11);
        o20 = fmaf(x.z, u.x, o20); o21 = fmaf(x.z, u.y, o21);
        o30 = fmaf(x.w, u.x, o30); o31 = fmaf(x.w, u.y, o31);
    }

    const float2 p_og1  = *(const float2*)(og1  + c0);
    const float2 p_obt1 = *(const float2*)(obt1 + c0);
    float g0[4], g1[4];
    float ov0[4] = {o00, o10, o20, o30};
    float ov1[4] = {o01, o11, o21, o31};
#pragma unroll
    for (int v = 0; v < 4; v++) {
        float b0 = ov0[v], b1 = ov1[v];
        float s  = bfly_sum(b0 + b1);
        float ss = bfly_sum(fmaf(b0, b0, b1 * b1));
        float mean = s * (1.0f / 64.0f);
        float var  = ss * (1.0f / 64.0f) - mean * mean;
        float rstd = rsqrtf(var + 1e-5f);
        g0[v] = gelu_tanh(fmaf((b0 - mean) * rstd, p_og1.x, p_obt1.x));
        g1[v] = gelu_tanh(fmaf((b1 - mean) * rstd, p_og1.y, p_obt1.y));
    }
    __syncwarp();
    s_x[w][c0]     = make_float4(g0[0], g0[1], g0[2], g0[3]);
    s_x[w][c0 + 1] = make_float4(g1[0], g1[1], g1[2], g1[3]);
    __syncwarp();

    const float2 p_ob2 = *(const float2*)(ob2 + c0);
    float f00 = p_ob2.x, f01 = p_ob2.y, f10 = p_ob2.x, f11 = p_ob2.y;
    float f20 = p_ob2.x, f21 = p_ob2.y, f30 = p_ob2.x, f31 = p_ob2.y;
#pragma unroll 8
    for (int j = 0; j < CO; j++) {
        float4 x = s_x[w][j];
        float2 u = __ldg((const float2*)(ow2 + j * CO + c0));
        f00 = fmaf(x.x, u.x, f00); f01 = fmaf(x.x, u.y, f01);
        f10 = fmaf(x.y, u.x, f10); f11 = fmaf(x.y, u.y, f11);
        f20 = fmaf(x.z, u.x, f20); f21 = fmaf(x.z, u.y, f21);
        f30 = fmaf(x.w, u.x, f30); f31 = fmaf(x.w, u.y, f31);
    }
    *(float2*)(out + (v0 + 0) * CO + c0) = make_float2(f00, f01);
    *(float2*)(out + (v0 + 1) * CO + c0) = make_float2(f10, f11);
    *(float2*)(out + (v0 + 2) * CO + c0) = make_float2(f20, f21);
    *(float2*)(out + (v0 + 3) * CO + c0) = make_float2(f30, f31);
}

// ---------------------------------------------------------------------------
extern "C" void kernel_launch(void* const* d_in, const int* in_sizes, int n_in,
                              void* d_out, int out_size) {
    const float* vertices = (const float*)d_in[0];
    const float* features = (const float*)d_in[1];
    const float* gverts   = (const float*)d_in[2];
    const float* gfeat    = (const float*)d_in[3];
    const float* ew1  = (const float*)d_in[4];
    const float* eb1  = (const float*)d_in[5];
    const float* eg1  = (const float*)d_in[6];
    const float* ebt1 = (const float*)d_in[7];
    const float* ew2  = (const float*)d_in[8];
    const float* eb2  = (const float*)d_in[9];
    const float* ow1  = (const float*)d_in[10];
    const float* ob1  = (const float*)d_in[11];
    const float* og1  = (const float*)d_in[12];
    const float* obt1 = (const float*)d_in[13];
    const float* ow2  = (const float*)d_in[14];
    const float* ob2  = (const float*)d_in[15];
    float* out = (float*)d_out;

    bin_kernel<<<1, NCELLS>>>(vertices);
    knn_kernel<<<dim3(8, 8, 8), dim3(4, 4, 4)>>>(gverts);
    wscal_kernel<<<1, 32>>>(ew1);
    pre_kernel<<<N_PTS * 32 / 256, 256>>>(features, ew1, eb1);
    edge_kernel<<<M_TOT / 8, 256>>>(vertices, gverts, ew1, eg1, ebt1);
    out_kernel<<<M_TOT / 32, 256>>>(gfeat, ew2, eb2, ow1, ob1,
                                    og1, obt1, ow2, ob2, out);
}

// round 17
// speedup vs baseline: 6.8646x; 1.0419x over previous
#include <cuda_runtime.h>
#include <math.h>

#define M_TOT 32768
#define N_PTS 8192
#define KK    16
#define CIN   32
#define CO    64
#define NC1   8
#define NCELLS 512

// scratch (all __device__, no allocs)
__device__ int    g_cellid[N_PTS];
__device__ int    g_off[NCELLS + 1];
__device__ float4 g_pts[N_PTS];
__device__ int    g_pidx[N_PTS];
__device__ int    g_knn[M_TOT * KK];
__device__ float  g_gmean[M_TOT * CO];   // 8 MB: post-gelu K-mean
__device__ float  g_P[N_PTS * CO];       // 2 MB: feats@ew1[0:32] + eb1
__device__ float4 g_aux[N_PTS];          // (sP, sP2, d32, d33)
__device__ float  g_aux2[N_PTS];         // d34
__device__ float  g_wscal[9];

// 27 neighbor offsets ordered near-to-far
__constant__ signed char c_off[27][3] = {
    { 0, 0, 0},
    {-1, 0, 0}, { 1, 0, 0}, { 0,-1, 0}, { 0, 1, 0}, { 0, 0,-1}, { 0, 0, 1},
    {-1,-1, 0}, {-1, 1, 0}, { 1,-1, 0}, { 1, 1, 0},
    {-1, 0,-1}, {-1, 0, 1}, { 1, 0,-1}, { 1, 0, 1},
    { 0,-1,-1}, { 0,-1, 1}, { 0, 1,-1}, { 0, 1, 1},
    {-1,-1,-1}, {-1,-1, 1}, {-1, 1,-1}, {-1, 1, 1},
    { 1,-1,-1}, { 1,-1, 1}, { 1, 1,-1}, { 1, 1, 1}
};

__device__ __forceinline__ float gelu_tanh(float x) {
    float x3  = x * x * x;
    float arg = 0.7978845608028654f * (x + 0.044715f * x3);
    float t;
    asm("tanh.approx.f32 %0, %1;" : "=f"(t) : "f"(arg));
    return 0.5f * x * (1.0f + t);
}

__device__ __forceinline__ float bfly_sum(float v) {
#pragma unroll
    for (int o = 16; o > 0; o >>= 1)
        v += __shfl_xor_sync(0xffffffffu, v, o);
    return v;
}

// order-preserving float <-> uint32
__device__ __forceinline__ unsigned int f2ord(float f) {
    unsigned int u = __float_as_uint(f);
    return (u & 0x80000000u) ? ~u : (u | 0x80000000u);
}
__device__ __forceinline__ float ord2f(unsigned int o) {
    unsigned int u = (o & 0x80000000u) ? (o & 0x7fffffffu) : ~o;
    return __uint_as_float(u);
}

// ---------------------------------------------------------------------------
// Fused binning (UNCHANGED, verified)
// ---------------------------------------------------------------------------
__global__ __launch_bounds__(NCELLS) void bin_kernel(const float* __restrict__ verts) {
    __shared__ int s_cnt[NCELLS];
    __shared__ int s_scan[NCELLS];
    const int t = threadIdx.x;
    s_cnt[t] = 0;
    __syncthreads();

    for (int i = t; i < N_PTS; i += NCELLS) {
        float rx = __fmul_rn(verts[i * 3 + 0], 32.0f);
        float ry = __fmul_rn(verts[i * 3 + 1], 32.0f);
        float rz = __fmul_rn(verts[i * 3 + 2], 32.0f);
        int cx = min(NC1 - 1, max(0, (int)(rx * 0.25f)));
        int cy = min(NC1 - 1, max(0, (int)(ry * 0.25f)));
        int cz = min(NC1 - 1, max(0, (int)(rz * 0.25f)));
        int c  = (cx * NC1 + cy) * NC1 + cz;
        g_cellid[i] = c;
        atomicAdd(&s_cnt[c], 1);
    }
    __syncthreads();

    int v = s_cnt[t];
    s_scan[t] = v;
    __syncthreads();
    for (int o = 1; o < NCELLS; o <<= 1) {
        int x = (t >= o) ? s_scan[t - o] : 0;
        __syncthreads();
        s_scan[t] += x;
        __syncthreads();
    }
    g_off[t + 1] = s_scan[t];
    if (t == 0) g_off[0] = 0;
    s_cnt[t] = s_scan[t] - v;
    __syncthreads();

    for (int i = t; i < N_PTS; i += NCELLS) {
        float rx = __fmul_rn(verts[i * 3 + 0], 32.0f);
        float ry = __fmul_rn(verts[i * 3 + 1], 32.0f);
        float rz = __fmul_rn(verts[i * 3 + 2], 32.0f);
        float B  = __fadd_rn(__fadd_rn(__fmul_rn(rx, rx), __fmul_rn(ry, ry)),
                             __fmul_rn(rz, rz));
        int c   = g_cellid[i];
        int pos = atomicAdd(&s_cnt[c], 1);
        g_pts[pos]  = make_float4(rx, ry, rz, B);
        g_pidx[pos] = i;
    }
}

// ---------------------------------------------------------------------------
// Weight scalars (UNCHANGED, verified)
// ---------------------------------------------------------------------------
__global__ void wscal_kernel(const float* __restrict__ ew1) {
    const int lane = threadIdx.x;
    const int c0   = lane * 2;
    float2 w32 = __ldg((const float2*)(ew1 + 32 * CO + c0));
    float2 w33 = __ldg((const float2*)(ew1 + 33 * CO + c0));
    float2 w34 = __ldg((const float2*)(ew1 + 34 * CO + c0));
    float r0 = bfly_sum(w32.x + w32.y);
    float r1 = bfly_sum(w33.x + w33.y);
    float r2 = bfly_sum(w34.x + w34.y);
    float r3 = bfly_sum(fmaf(w32.x, w32.x, w32.y * w32.y));
    float r4 = bfly_sum(fmaf(w33.x, w33.x, w33.y * w33.y));
    float r5 = bfly_sum(fmaf(w34.x, w34.x, w34.y * w34.y));
    float r6 = bfly_sum(fmaf(w32.x, w33.x, w32.y * w33.y));
    float r7 = bfly_sum(fmaf(w32.x, w34.x, w32.y * w34.y));
    float r8 = bfly_sum(fmaf(w33.x, w34.x, w33.y * w34.y));
    if (lane == 0) {
        g_wscal[0] = r0; g_wscal[1] = r1; g_wscal[2] = r2;
        g_wscal[3] = r3; g_wscal[4] = r4; g_wscal[5] = r5;
        g_wscal[6] = r6; g_wscal[7] = r7; g_wscal[8] = r8;
    }
}

// ---------------------------------------------------------------------------
// Precompute P' + per-point LN aggregates (UNCHANGED, verified @8.2us)
// ---------------------------------------------------------------------------
__global__ __launch_bounds__(256) void pre_kernel(const float* __restrict__ feats,
                                                  const float* __restrict__ ew1,
                                                  const float* __restrict__ eb1) {
    const int n    = (blockIdx.x * 256 + threadIdx.x) >> 5;
    const int lane = threadIdx.x & 31;
    const int c0   = lane * 2;
    const float* f = feats + n * CIN;
    float2 b = __ldg((const float2*)(eb1 + c0));
    float a0 = b.x, a1 = b.y;
#pragma unroll
    for (int i = 0; i < CIN; i++) {
        float  fv = __ldg(f + i);
        float2 u  = __ldg((const float2*)(ew1 + i * CO + c0));
        a0 = fmaf(fv, u.x, a0);
        a1 = fmaf(fv, u.y, a1);
    }
    *(float2*)(g_P + n * CO + c0) = make_float2(a0, a1);

    float2 w32 = __ldg((const float2*)(ew1 + 32 * CO + c0));
    float2 w33 = __ldg((const float2*)(ew1 + 33 * CO + c0));
    float2 w34 = __ldg((const float2*)(ew1 + 34 * CO + c0));
    float sp  = bfly_sum(a0 + a1);
    float sp2 = bfly_sum(fmaf(a0, a0, a1 * a1));
    float d32 = bfly_sum(fmaf(a0, w32.x, a1 * w32.y));
    float d33 = bfly_sum(fmaf(a0, w33.x, a1 * w33.y));
    float d34 = bfly_sum(fmaf(a0, w34.x, a1 * w34.y));
    if (lane == 0) {
        g_aux[n]  = make_float4(sp, sp2, d32, d33);
        g_aux2[n] = d34;
    }
}

// ---------------------------------------------------------------------------
// KNN split-2: 2 threads per query (parity over each cell segment), private
// top-16 each, then shfl rank-merge. cx/cy/cz are block-uniform (each aligned
// 4-index tile maps into one cell: cell(i) = floor(8i/31)), so every warp
// vote is executed by all 32 lanes. Warp-uniform ring termination via
// __all_sync is conservative (private worstf >= combined worst).
// ---------------------------------------------------------------------------
__global__ __launch_bounds__(128) void knn_kernel(const float* __restrict__ gverts) {
    const int tid = threadIdx.x;
    const int qid = tid >> 1;
    const int par = tid & 1;
    const int ix = blockIdx.x * 4 + (qid >> 4);
    const int iy = blockIdx.y * 4 + ((qid >> 2) & 3);
    const int iz = blockIdx.z * 4 + (qid & 3);
    const int m  = (ix * 32 + iy) * 32 + iz;

    const float qx = __fmul_rn(gverts[m * 3 + 0], 32.0f);
    const float qy = __fmul_rn(gverts[m * 3 + 1], 32.0f);
    const float qz = __fmul_rn(gverts[m * 3 + 2], 32.0f);
    const float A  = __fadd_rn(__fadd_rn(__fmul_rn(qx, qx), __fmul_rn(qy, qy)),
                               __fmul_rn(qz, qz));

    const int cx = min(NC1 - 1, max(0, (int)(qx * 0.25f)));
    const int cy = min(NC1 - 1, max(0, (int)(qy * 0.25f)));
    const int cz = min(NC1 - 1, max(0, (int)(qz * 0.25f)));

    const unsigned long long SENT =
        ((unsigned long long)f2ord(3.0e38f) << 32) | 0xffffffffull;
    unsigned long long kkey[KK];
#pragma unroll
    for (int t = 0; t < KK; t++) kkey[t] = SENT;
    unsigned long long worstkey = SENT;
    float worstf = 3.0e38f;
    int   wpos   = 0;

    // ---- r=1: 27 cells near-to-far with warp-cooperative culling ----
    for (int ci = 0; ci < 27; ci++) {
        const int xx = cx + c_off[ci][0];
        const int yy = cy + c_off[ci][1];
        const int zz = cz + c_off[ci][2];
        if (xx < 0 || xx >= NC1 || yy < 0 || yy >= NC1 ||
            zz < 0 || zz >= NC1) continue;

        float lox = (float)(4 * xx), loy = (float)(4 * yy), loz = (float)(4 * zz);
        float dx = fmaxf(0.0f, fmaxf(lox - qx, qx - (lox + 4.0f)));
        float dy = fmaxf(0.0f, fmaxf(loy - qy, qy - (loy + 4.0f)));
        float dz = fmaxf(0.0f, fmaxf(loz - qz, qz - (loz + 4.0f)));
        float cm2 = fmaf(dx, dx, fmaf(dy, dy, dz * dz));
        if (!__any_sync(0xffffffffu, cm2 <= worstf + 0.01f)) continue;

        const int c = (xx * NC1 + yy) * NC1 + zz;
        const int s = g_off[c], e = g_off[c + 1];
        for (int p = s + par; p < e; p += 2) {
            float4 pt = g_pts[p];
            float  D  = fmaf(qz, pt.z, fmaf(qy, pt.y, __fmul_rn(qx, pt.x)));
            float  d2 = __fsub_rn(__fadd_rn(A, pt.w), __fmul_rn(2.0f, D));
            if (d2 <= worstf) {
                unsigned long long key =
                    ((unsigned long long)f2ord(d2) << 32) |
                    (unsigned int)g_pidx[p];
                if (key < worstkey) {
#pragma unroll
                    for (int t = 0; t < KK; t++)
                        if (t == wpos) kkey[t] = key;
                    worstkey = kkey[0]; wpos = 0;
#pragma unroll
                    for (int t = 1; t < KK; t++)
                        if (kkey[t] > worstkey) { worstkey = kkey[t]; wpos = t; }
                    worstf = ord2f((unsigned int)(worstkey >> 32));
                }
            }
        }
    }

    // ---- rare fallback: rings r>=2, warp-uniform termination ----
    int px0 = max(cx - 1, 0), px1 = min(cx + 1, NC1 - 1);
    int py0 = max(cy - 1, 0), py1 = min(cy + 1, NC1 - 1);
    int pz0 = max(cz - 1, 0), pz1 = min(cz + 1, NC1 - 1);

    for (int r = 1; r <= NC1; r++) {
        float cov = 1e30f;
        if (px0 > 0)       cov = fminf(cov, qx - (float)px0 * 4.0f);
        if (px1 < NC1 - 1) cov = fminf(cov, (float)(px1 + 1) * 4.0f - qx);
        if (py0 > 0)       cov = fminf(cov, qy - (float)py0 * 4.0f);
        if (py1 < NC1 - 1) cov = fminf(cov, (float)(py1 + 1) * 4.0f - qy);
        if (pz0 > 0)       cov = fminf(cov, qz - (float)pz0 * 4.0f);
        if (pz1 < NC1 - 1) cov = fminf(cov, (float)(pz1 + 1) * 4.0f - qz);
        if (__all_sync(0xffffffffu,
                       worstf <= cov * cov * 0.999f - 1e-3f)) break;

        const int rr = r + 1;
        const int nx0 = max(cx - rr, 0), nx1 = min(cx + rr, NC1 - 1);
        const int ny0 = max(cy - rr, 0), ny1 = min(cy + rr, NC1 - 1);
        const int nz0 = max(cz - rr, 0), nz1 = min(cz + rr, NC1 - 1);
        if (nx0 == px0 && nx1 == px1 && ny0 == py0 && ny1 == py1 &&
            nz0 == pz0 && nz1 == pz1) break;   // whole domain scanned

        for (int x = nx0; x <= nx1; x++)
        for (int y = ny0; y <= ny1; y++)
        for (int z = nz0; z <= nz1; z++) {
            if (x >= px0 && x <= px1 && y >= py0 && y <= py1 &&
                z >= pz0 && z <= pz1) continue;
            float lox = (float)(4 * x), loy = (float)(4 * y), loz = (float)(4 * z);
            float dx = fmaxf(0.0f, fmaxf(lox - qx, qx - (lox + 4.0f)));
            float dy = fmaxf(0.0f, fmaxf(loy - qy, qy - (loy + 4.0f)));
            float dz = fmaxf(0.0f, fmaxf(loz - qz, qz - (loz + 4.0f)));
            float cm2 = fmaf(dx, dx, fmaf(dy, dy, dz * dz));
            if (!__any_sync(0xffffffffu, cm2 <= worstf + 0.01f)) continue;

            const int c = (x * NC1 + y) * NC1 + z;
            const int s = g_off[c], e = g_off[c + 1];
            for (int p = s + par; p < e; p += 2) {
                float4 pt = g_pts[p];
                float  D  = fmaf(qz, pt.z, fmaf(qy, pt.y, __fmul_rn(qx, pt.x)));
                float  d2 = __fsub_rn(__fadd_rn(A, pt.w), __fmul_rn(2.0f, D));
                if (d2 <= worstf) {
                    unsigned long long key =
                        ((unsigned long long)f2ord(d2) << 32) |
                        (unsigned int)g_pidx[p];
                    if (key < worstkey) {
#pragma unroll
                        for (int t = 0; t < KK; t++)
                            if (t == wpos) kkey[t] = key;
                        worstkey = kkey[0]; wpos = 0;
#pragma unroll
                        for (int t = 1; t < KK; t++)
                            if (kkey[t] > worstkey) { worstkey = kkey[t]; wpos = t; }
                        worstf = ord2f((unsigned int)(worstkey >> 32));
                    }
                }
            }
        }
        px0 = nx0; px1 = nx1; py0 = ny0; py1 = ny1; pz0 = nz0; pz1 = nz1;
    }

    // ---- sort my 16 ascending (odd-even network, registers) ----
#pragma unroll
    for (int rd = 0; rd < KK; rd++) {
#pragma unroll
        for (int t = (rd & 1); t + 1 < KK; t += 2) {
            if (kkey[t] > kkey[t + 1]) {
                unsigned long long tmp = kkey[t]; kkey[t] = kkey[t + 1]; kkey[t + 1] = tmp;
            }
        }
    }

    // ---- pair rank-merge: rank = own position + #(partner keys < mine) ----
    int cnt[KK];
#pragma unroll
    for (int t = 0; t < KK; t++) cnt[t] = 0;
#pragma unroll
    for (int j = 0; j < KK; j++) {
        unsigned long long pk = __shfl_xor_sync(0xffffffffu, kkey[j], 1);
#pragma unroll
        for (int t = 0; t < KK; t++) cnt[t] += (pk < kkey[t]);
    }
#pragma unroll
    for (int t = 0; t < KK; t++) {
        int rank = t + cnt[t];
        if (rank < KK) g_knn[m * KK + rank] = (int)(kkey[t] & 0xffffffffu);
    }
}

// ---------------------------------------------------------------------------
// Edge kernel with analytic LN stats (UNCHANGED, verified @R15)
// ---------------------------------------------------------------------------
__global__ __launch_bounds__(256) void edge_kernel(
    const float* __restrict__ verts, const float* __restrict__ gverts,
    const float* __restrict__ ew1,
    const float* __restrict__ eg1, const float* __restrict__ ebt1)
{
    __shared__ int   s_idx[8][KK];
    __shared__ float s_rp[8][KK][4];

    const int tid  = threadIdx.x;
    const int w    = tid >> 5;
    const int lane = tid & 31;
    const int m    = blockIdx.x * 8 + w;
    const int c0   = lane * 2;

    const float2 w32 = __ldg((const float2*)(ew1 + 32 * CO + c0));
    const float2 w33 = __ldg((const float2*)(ew1 + 33 * CO + c0));
    const float2 w34 = __ldg((const float2*)(ew1 + 34 * CO + c0));
    const float2 p_eg1  = *(const float2*)(eg1  + c0);
    const float2 p_ebt1 = *(const float2*)(ebt1 + c0);

    const float sw32 = __ldg(&g_wscal[0]), sw33 = __ldg(&g_wscal[1]);
    const float sw34 = __ldg(&g_wscal[2]);
    const float s3232 = __ldg(&g_wscal[3]), s3333 = __ldg(&g_wscal[4]);
    const float s3434 = __ldg(&g_wscal[5]);
    const float s3233 = __ldg(&g_wscal[6]), s3234 = __ldg(&g_wscal[7]);
    const float s3334 = __ldg(&g_wscal[8]);

    if (lane < KK) {
        int idx = g_knn[m * KK + lane];
        s_idx[w][lane] = idx;
        s_rp[w][lane][0] = verts[idx * 3 + 0] - gverts[m * 3 + 0];
        s_rp[w][lane][1] = verts[idx * 3 + 1] - gverts[m * 3 + 1];
        s_rp[w][lane][2] = verts[idx * 3 + 2] - gverts[m * 3 + 2];
    }
    __syncwarp();

    float my_mean = 0.0f, my_rstd = 1.0f;
    if (lane < KK) {
        int    idxr = s_idx[w][lane];
        float  rx = s_rp[w][lane][0];
        float  ry = s_rp[w][lane][1];
        float  rz = s_rp[w][lane][2];
        float4 au   = __ldg(&g_aux[idxr]);
        float  d34v = __ldg(&g_aux2[idxr]);
        float sum = au.x + rx * sw32 + ry * sw33 + rz * sw34;
        float ss  = au.y
                  + 2.0f * (rx * au.z + ry * au.w + rz * d34v)
                  + rx * rx * s3232 + ry * ry * s3333 + rz * rz * s3434
                  + 2.0f * (rx * ry * s3233 + rx * rz * s3234 + ry * rz * s3334);
        my_mean = sum * (1.0f / 64.0f);
        float var = ss * (1.0f / 64.0f) - my_mean * my_mean;
        my_rstd = rsqrtf(var + 1e-5f);
    }
    __syncwarp();

    float gb0 = 0.0f, gb1 = 0.0f;
#pragma unroll
    for (int r = 0; r < KK; r++) {
        float mean = __shfl_sync(0xffffffffu, my_mean, r);
        float rstd = __shfl_sync(0xffffffffu, my_rstd, r);
        int    idx = s_idx[w][r];
        float  rx  = s_rp[w][r][0];
        float  ry  = s_rp[w][r][1];
        float  rz  = s_rp[w][r][2];
        float2 p   = __ldg((const float2*)(g_P + idx * CO + c0));
        float a0 = p.x, a1 = p.y;
        a0 = fmaf(rx, w32.x, a0); a1 = fmaf(rx, w32.y, a1);
        a0 = fmaf(ry, w33.x, a0); a1 = fmaf(ry, w33.y, a1);
        a0 = fmaf(rz, w34.x, a0); a1 = fmaf(rz, w34.y, a1);
        float h0 = fmaf((a0 - mean) * rstd, p_eg1.x, p_ebt1.x);
        float h1 = fmaf((a1 - mean) * rstd, p_eg1.y, p_ebt1.y);
        gb0 += gelu_tanh(h0);
        gb1 += gelu_tanh(h1);
    }
    gb0 *= (1.0f / 16.0f);
    gb1 *= (1.0f / 16.0f);
    *(float2*)(g_gmean + m * CO + c0) = make_float2(gb0, gb1);
}

// ---------------------------------------------------------------------------
// Out kernel (UNCHANGED, verified)
// ---------------------------------------------------------------------------
__global__ __launch_bounds__(256) void out_kernel(
    const float* __restrict__ gfeat,
    const float* __restrict__ ew2, const float* __restrict__ eb2,
    const float* __restrict__ ow1, const float* __restrict__ ob1,
    const float* __restrict__ og1, const float* __restrict__ obt1,
    const float* __restrict__ ow2, const float* __restrict__ ob2,
    float* __restrict__ out)
{
    __shared__ __align__(16) float4 s_x[8][160];

    const int tid  = threadIdx.x;
    const int w    = tid >> 5;
    const int lane = tid & 31;
    const int c0   = lane * 2;
    const int v0   = blockIdx.x * 32 + w * 4;

    for (int i = lane; i < CO; i += 32)
        s_x[w][i] = make_float4(g_gmean[(v0 + 0) * CO + i], g_gmean[(v0 + 1) * CO + i],
                                g_gmean[(v0 + 2) * CO + i], g_gmean[(v0 + 3) * CO + i]);
    for (int i = lane; i < 96; i += 32)
        s_x[w][CO + i] = make_float4(gfeat[(v0 + 0) * 96 + i], gfeat[(v0 + 1) * 96 + i],
                                     gfeat[(v0 + 2) * 96 + i], gfeat[(v0 + 3) * 96 + i]);
    __syncwarp();

    const float2 p_eb2 = *(const float2*)(eb2 + c0);
    float a00 = p_eb2.x, a01 = p_eb2.y, a10 = p_eb2.x, a11 = p_eb2.y;
    float a20 = p_eb2.x, a21 = p_eb2.y, a30 = p_eb2.x, a31 = p_eb2.y;
#pragma unroll 8
    for (int i = 0; i < CO; i++) {
        float4 x = s_x[w][i];
        float2 u = __ldg((const float2*)(ew2 + i * CO + c0));
        a00 = fmaf(x.x, u.x, a00); a01 = fmaf(x.x, u.y, a01);
        a10 = fmaf(x.y, u.x, a10); a11 = fmaf(x.y, u.y, a11);
        a20 = fmaf(x.z, u.x, a20); a21 = fmaf(x.z, u.y, a21);
        a30 = fmaf(x.w, u.x, a30); a31 = fmaf(x.w, u.y, a31);
    }
    __syncwarp();
    s_x[w][c0]     = make_float4(a00, a10, a20, a30);
    s_x[w][c0 + 1] = make_float4(a01, a11, a21, a31);
    __syncwarp();

    const float2 p_ob1 = *(const float2*)(ob1 + c0);
    float o00 = p_ob1.x, o01 = p_ob1.y, o10 = p_ob1.x, o11 = p_ob1.y;
    float o20 = p_ob1.x, o21 = p_ob1.y, o30 = p_ob1.x, o31 = p_ob1.y;
#pragma unroll 8
    for (int i = 0; i < CO + 96; i++) {
        float4 x = s_x[w][i];
        float2 u = __ldg((const float2*)(ow1 + i * CO + c0));
        o00 = fmaf(x.x, u.x, o00); o01 = fmaf(x.x, u.y, o01);
        o10 = fmaf(x.y, u.x, o10); o11 = fmaf(x.y, u.y, o11);
        o20 = fmaf(x.z, u.x, o20); o21 = fmaf(x.z, u.y, o21);
        o30 = fmaf(x.w, u.x, o30); o31 = fmaf(x.w, u.y, o31);
    }

    const float2 p_og1  = *(const float2*)(og1  + c0);
    const float2 p_obt1 = *(const float2*)(obt1 + c0);
    float g0[4], g1[4];
    float ov0[4] = {o00, o10, o20, o30};
    float ov1[4] = {o01, o11, o21, o31};
#pragma unroll
    for (int v = 0; v < 4; v++) {
        float b0 = ov0[v], b1 = ov1[v];
        float s  = bfly_sum(b0 + b1);
        float ss = bfly_sum(fmaf(b0, b0, b1 * b1));
        float mean = s * (1.0f / 64.0f);
        float var  = ss * (1.0f / 64.0f) - mean * mean;
        float rstd = rsqrtf(var + 1e-5f);
        g0[v] = gelu_tanh(fmaf((b0 - mean) * rstd, p_og1.x, p_obt1.x));
        g1[v] = gelu_tanh(fmaf((b1 - mean) * rstd, p_og1.y, p_obt1.y));
    }
    __syncwarp();
    s_x[w][c0]     = make_float4(g0[0], g0[1], g0[2], g0[3]);
    s_x[w][c0 + 1] = make_float4(g1[0], g1[1], g1[2], g1[3]);
    __syncwarp();

    const float2 p_ob2 = *(const float2*)(ob2 + c0);
    float f00 = p_ob2.x, f01 = p_ob2.y, f10 = p_ob2.x, f11 = p_ob2.y;
    float f20 = p_ob2.x, f21 = p_ob2.y, f30 = p_ob2.x, f31 = p_ob2.y;
#pragma unroll 8
    for (int j = 0; j < CO; j++) {
        float4 x = s_x[w][j];
        float2 u = __ldg((const float2*)(ow2 + j * CO + c0));
        f00 = fmaf(x.x, u.x, f00); f01 = fmaf(x.x, u.y, f01);
        f10 = fmaf(x.y, u.x, f10); f11 = fmaf(x.y, u.y, f11);
        f20 = fmaf(x.z, u.x, f20); f21 = fmaf(x.z, u.y, f21);
        f30 = fmaf(x.w, u.x, f30); f31 = fmaf(x.w, u.y, f31);
    }
    *(float2*)(out + (v0 + 0) * CO + c0) = make_float2(f00, f01);
    *(float2*)(out + (v0 + 1) * CO + c0) = make_float2(f10, f11);
    *(float2*)(out + (v0 + 2) * CO + c0) = make_float2(f20, f21);
    *(float2*)(out + (v0 + 3) * CO + c0) = make_float2(f30, f31);
}

// ---------------------------------------------------------------------------
extern "C" void kernel_launch(void* const* d_in, const int* in_sizes, int n_in,
                              void* d_out, int out_size) {
    const float* vertices = (const float*)d_in[0];
    const float* features = (const float*)d_in[1];
    const float* gverts   = (const float*)d_in[2];
    const float* gfeat    = (const float*)d_in[3];
    const float* ew1  = (const float*)d_in[4];
    const float* eb1  = (const float*)d_in[5];
    const float* eg1  = (const float*)d_in[6];
    const float* ebt1 = (const float*)d_in[7];
    const float* ew2  = (const float*)d_in[8];
    const float* eb2  = (const float*)d_in[9];
    const float* ow1  = (const float*)d_in[10];
    const float* ob1  = (const float*)d_in[11];
    const float* og1  = (const float*)d_in[12];
    const float* obt1 = (const float*)d_in[13];
    const float* ow2  = (const float*)d_in[14];
    const float* ob2  = (const float*)d_in[15];
    float* out = (float*)d_out;

    bin_kernel<<<1, NCELLS>>>(vertices);
    knn_kernel<<<dim3(8, 8, 8), 128>>>(gverts);
    wscal_kernel<<<1, 32>>>(ew1);
    pre_kernel<<<N_PTS * 32 / 256, 256>>>(features, ew1, eb1);
    edge_kernel<<<M_TOT / 8, 256>>>(vertices, gverts, ew1, eg1, ebt1);
    out_kernel<<<M_TOT / 32, 256>>>(gfeat, ew2, eb2, ow1, ob1,
                                    og1, obt1, ow2, ob2, out);
}